// round 13
// baseline (speedup 1.0000x reference)
#include <cuda_runtime.h>
#include <cuda_bf16.h>
#include <cuda_fp16.h>
#include <cstdint>

#define N_NODES 50000
#define NPAD    50048            // 391 * 128
#define H_DIM   128
#define F_DIM   256
#define C_DIM   40
#define CPAD    64
#define E_CAP   800000
#define SCAN_B  196              // ceil(NPAD / 256)

// ---------------------------------------------------------------------------
// Global scratch (static device globals)
// ---------------------------------------------------------------------------
__device__ float  g_X[NPAD * H_DIM];     // activations (plain fp32)
__device__ __half g_Hh[NPAD * H_DIM];    // x @ W, row-scaled, fp16 messages
__device__ float  g_degout[NPAD];        // rsqrt(max(deg_out,1))
__device__ float  g_degin [NPAD];
__device__ int    g_cntin[NPAD], g_cntout[NPAD], g_cnt2[NPAD];
__device__ int    g_rowstart[NPAD + 1];
__device__ int    g_srcsorted[E_CAP];
__device__ int    g_blocksum[SCAN_B];
__device__ int    g_blockoff[SCAN_B];
// weights pre-split to bf16 hi/lo, TRANSPOSED to [N x K] row-major
__device__ __nv_bfloat16 gWp_hi[H_DIM * F_DIM], gWp_lo[H_DIM * F_DIM];
__device__ __nv_bfloat16 gW1_hi[H_DIM * H_DIM], gW1_lo[H_DIM * H_DIM];
__device__ __nv_bfloat16 gW2_hi[H_DIM * H_DIM], gW2_lo[H_DIM * H_DIM];
__device__ __nv_bfloat16 gWc_hi[CPAD  * H_DIM], gWc_lo[CPAD  * H_DIM];

// ---------------------------------------------------------------------------
// CSR build + degree kernels
// ---------------------------------------------------------------------------
__global__ void zero_cnt_kernel() {
    int i = blockIdx.x * blockDim.x + threadIdx.x;
    if (i < NPAD) { g_cntin[i] = 0; g_cntout[i] = 0; g_cnt2[i] = 0; }
}

__global__ void count_kernel(const int* __restrict__ src, const int* __restrict__ dst, int E) {
    int i = blockIdx.x * blockDim.x + threadIdx.x;
    if (i < E) {
        atomicAdd(&g_cntout[src[i]], 1);
        atomicAdd(&g_cntin[dst[i]], 1);
    }
}

__global__ void rsqrt_kernel() {
    int i = blockIdx.x * blockDim.x + threadIdx.x;
    if (i < NPAD) {
        g_degout[i] = rsqrtf((float)max(g_cntout[i], 1));
        g_degin[i]  = rsqrtf((float)max(g_cntin[i], 1));
    }
}

// ---- 3-phase multi-block exclusive scan of g_cntin -> g_rowstart ----------
__global__ void scan_phaseA() {
    int t = threadIdx.x;
    int idx = blockIdx.x * 256 + t;
    int v = (idx < NPAD) ? g_cntin[idx] : 0;
    #pragma unroll
    for (int o = 16; o; o >>= 1) v += __shfl_down_sync(0xffffffffu, v, o);
    __shared__ int ws[8];
    if ((t & 31) == 0) ws[t >> 5] = v;
    __syncthreads();
    if (t < 8) {
        int s = ws[t];
        #pragma unroll
        for (int o = 4; o; o >>= 1) s += __shfl_down_sync(0xffu, s, o);
        if (t == 0) g_blocksum[blockIdx.x] = s;
    }
}

__global__ void scan_phaseB() {
    int t = threadIdx.x;
    int lane = t & 31, w = t >> 5;
    int v = (t < SCAN_B) ? g_blocksum[t] : 0;
    int x = v;
    #pragma unroll
    for (int o = 1; o < 32; o <<= 1) {
        int y = __shfl_up_sync(0xffffffffu, x, o);
        if (lane >= o) x += y;
    }
    __shared__ int ws[8];
    if (lane == 31) ws[w] = x;
    __syncthreads();
    if (t == 0) {
        int s = 0;
        #pragma unroll
        for (int i = 0; i < 8; i++) { int tmp = ws[i]; ws[i] = s; s += tmp; }
    }
    __syncthreads();
    int incl = x + ws[w];
    if (t < SCAN_B) {
        g_blockoff[t] = incl - v;
        if (t == SCAN_B - 1) g_rowstart[NPAD] = incl;
    }
}

__global__ void scan_phaseC() {
    int t = threadIdx.x;
    int idx = blockIdx.x * 256 + t;
    int lane = t & 31, w = t >> 5;
    int v = (idx < NPAD) ? g_cntin[idx] : 0;
    int x = v;
    #pragma unroll
    for (int o = 1; o < 32; o <<= 1) {
        int y = __shfl_up_sync(0xffffffffu, x, o);
        if (lane >= o) x += y;
    }
    __shared__ int ws[8];
    if (lane == 31) ws[w] = x;
    __syncthreads();
    if (t == 0) {
        int s = 0;
        #pragma unroll
        for (int i = 0; i < 8; i++) { int tmp = ws[i]; ws[i] = s; s += tmp; }
    }
    __syncthreads();
    int excl = x - v + ws[w] + g_blockoff[blockIdx.x];
    if (idx < NPAD) g_rowstart[idx] = excl;
}

__global__ void scatter_kernel(const int* __restrict__ src, const int* __restrict__ dst, int E) {
    int i = blockIdx.x * blockDim.x + threadIdx.x;
    if (i < E) {
        int d = dst[i];
        int pos = g_rowstart[d] + atomicAdd(&g_cnt2[d], 1);
        g_srcsorted[pos] = src[i];
    }
}

// ---------------------------------------------------------------------------
// CSR aggregate + finalize: one warp per dst node, fp16 messages.
// ---------------------------------------------------------------------------
__global__ void csr_agg_kernel(const float* __restrict__ bias) {
    int warp = (blockIdx.x * blockDim.x + threadIdx.x) >> 5;
    int lane = threadIdx.x & 31;
    if (warp >= NPAD) return;
    int beg = g_rowstart[warp];
    int end = g_rowstart[warp + 1];
    float4 acc = make_float4(0.f, 0.f, 0.f, 0.f);
    const uint2* Hv = reinterpret_cast<const uint2*>(g_Hh);

    auto addrow = [&](int s) {
        uint2 u = Hv[s * 32 + lane];
        __half2 p0 = *reinterpret_cast<__half2*>(&u.x);
        __half2 p1 = *reinterpret_cast<__half2*>(&u.y);
        float2 f0 = __half22float2(p0);
        float2 f1 = __half22float2(p1);
        acc.x += f0.x; acc.y += f0.y; acc.z += f1.x; acc.w += f1.y;
    };

    int e = beg;
    for (; e + 7 < end; e += 8) {
        int s0 = g_srcsorted[e],   s1 = g_srcsorted[e+1], s2 = g_srcsorted[e+2], s3 = g_srcsorted[e+3];
        int s4 = g_srcsorted[e+4], s5 = g_srcsorted[e+5], s6 = g_srcsorted[e+6], s7 = g_srcsorted[e+7];
        addrow(s0); addrow(s1); addrow(s2); addrow(s3);
        addrow(s4); addrow(s5); addrow(s6); addrow(s7);
    }
    for (; e < end; e++) addrow(g_srcsorted[e]);

    float rs = g_degin[warp];
    float4 b = reinterpret_cast<const float4*>(bias)[lane];
    float4 x;
    x.x = fmaxf(acc.x * rs + b.x, 0.f);
    x.y = fmaxf(acc.y * rs + b.y, 0.f);
    x.z = fmaxf(acc.z * rs + b.z, 0.f);
    x.w = fmaxf(acc.w * rs + b.w, 0.f);
    reinterpret_cast<float4*>(g_X)[warp * 32 + lane] = x;
}

// ---------------------------------------------------------------------------
// weight pre-split: W[K x N] -> bf16 hi/lo [Npad x K] (transposed, padded)
// ---------------------------------------------------------------------------
__device__ __forceinline__ void wsplit_one(const float* W, __nv_bfloat16* hi, __nv_bfloat16* lo,
                                           int K, int N, int Npad, int i) {
    int n = i / K, k = i - n * K;
    float v = (n < N) ? W[(size_t)k * N + n] : 0.f;
    __nv_bfloat16 h = __float2bfloat16_rn(v);
    float r = v - __bfloat162float(h);
    hi[i] = h;
    lo[i] = __float2bfloat16_rn(r);
}

__global__ void presplit_Wt_kernel(const float* __restrict__ W,
                                   __nv_bfloat16* __restrict__ hi,
                                   __nv_bfloat16* __restrict__ lo,
                                   int K, int N, int Npad) {
    int i = blockIdx.x * blockDim.x + threadIdx.x;
    if (i >= Npad * K) return;
    wsplit_one(W, hi, lo, K, N, Npad, i);
}

// merged presplit for W1, W2, Wc in one launch
__global__ void presplit_W12c_kernel(const float* __restrict__ W1,
                                     const float* __restrict__ W2,
                                     const float* __restrict__ Wc) {
    int i = blockIdx.x * blockDim.x + threadIdx.x;
    if (i < 16384) {
        wsplit_one(W1, gW1_hi, gW1_lo, H_DIM, H_DIM, H_DIM, i);
    } else if (i < 32768) {
        wsplit_one(W2, gW2_hi, gW2_lo, H_DIM, H_DIM, H_DIM, i - 16384);
    } else if (i < 40960) {
        wsplit_one(Wc, gWc_hi, gWc_lo, H_DIM, C_DIM, CPAD, i - 32768);
    }
}

// ---------------------------------------------------------------------------
// split-BF16 GEMM (3 products: hh + lh + hl): C[M,N] = A[M,K] @ Wt[N x K]
// BM=128, BN template (64/128), BK=32, 256 threads (8 warps: 4m x 2n),
// warp tile 32 x BN/2. A: LDG fp32 -> split -> STS -> ldmatrix.
// B: cp.async pre-split bf16 -> ldmatrix. mma.sync.m16n8k16.bf16.
// ---------------------------------------------------------------------------
__device__ __forceinline__ void cp16(uint32_t saddr, const void* g) {
    asm volatile("cp.async.ca.shared.global [%0], [%1], 16;" :: "r"(saddr), "l"(g) : "memory");
}

__device__ __forceinline__ void ldsm4(uint32_t& r0, uint32_t& r1, uint32_t& r2, uint32_t& r3,
                                      uint32_t saddr) {
    asm volatile("ldmatrix.sync.aligned.m8n8.x4.shared.b16 {%0,%1,%2,%3}, [%4];"
                 : "=r"(r0), "=r"(r1), "=r"(r2), "=r"(r3) : "r"(saddr));
}

__device__ __forceinline__ void mma_bf16(
    float& d0, float& d1, float& d2, float& d3,
    uint32_t a0, uint32_t a1, uint32_t a2, uint32_t a3,
    uint32_t b0, uint32_t b1)
{
    asm volatile(
        "mma.sync.aligned.m16n8k16.row.col.f32.bf16.bf16.f32 "
        "{%0,%1,%2,%3}, {%4,%5,%6,%7}, {%8,%9}, {%0,%1,%2,%3};"
        : "+f"(d0), "+f"(d1), "+f"(d2), "+f"(d3)
        : "r"(a0), "r"(a1), "r"(a2), "r"(a3), "r"(b0), "r"(b1));
}

// pack two floats' bf16 hi parts / lo parts
__device__ __forceinline__ void split_pack2(float x, float y, uint32_t& hi2, uint32_t& lo2) {
    __nv_bfloat162 h = __floats2bfloat162_rn(x, y);
    float rx = x - __bfloat162float(__low2bfloat16(h));
    float ry = y - __bfloat162float(__high2bfloat16(h));
    __nv_bfloat162 l = __floats2bfloat162_rn(rx, ry);
    hi2 = *reinterpret_cast<uint32_t*>(&h);
    lo2 = *reinterpret_cast<uint32_t*>(&l);
}

template<int BN>
__global__ __launch_bounds__(256) void mma_gemm_kernel(
    const float* __restrict__ A, int Mvalid,
    const __nv_bfloat16* __restrict__ Bhi, const __nv_bfloat16* __restrict__ Blo, int K,
    float* __restrict__ C, __half* __restrict__ Chalf, int ldC, int Mout, int Nout,
    const float* __restrict__ bias, const float* __restrict__ rowscale)
{
    constexpr int OFF_AL   = 10240;              // 128 * 80
    constexpr int OFF_BH   = 20480;
    constexpr int OFF_BL   = 20480 + BN * 80;
    constexpr int STG      = 20480 + 2 * BN * 80;
    constexpr int WN       = BN / 2;             // per-warp cols
    constexpr int NT       = WN / 8;             // 8-col n-tiles per warp
    constexpr int NP       = WN / 16;            // 16-col ldmatrix groups

    extern __shared__ uint8_t smem_raw[];
    const uint32_t smem_b = (uint32_t)__cvta_generic_to_shared(smem_raw);

    const int tid  = threadIdx.x;
    const int lane = tid & 31;
    const int warp = tid >> 5;
    const int wm   = warp >> 1;          // 0..3
    const int wn   = warp & 1;           // 0..1
    const int rowBase = blockIdx.y * 128;
    const int colBase = blockIdx.x * BN;
    const int nStages = K >> 5;

    float acc[2][NT][4];
    #pragma unroll
    for (int i = 0; i < 2; i++)
        #pragma unroll
        for (int j = 0; j < NT; j++)
            #pragma unroll
            for (int l = 0; l < 4; l++) acc[i][j][l] = 0.f;

    // A loader slots: 4 float4/thread; row = idx>>3, c4 = idx&7 (32 floats/row)
    int aRow[4], aC4[4];
    #pragma unroll
    for (int i = 0; i < 4; i++) {
        int idx = tid + i * 256;
        aRow[i] = idx >> 3;
        aC4[i]  = idx & 7;
    }

    float4 pa[4];
    auto loadA = [&](int s) {
        const int k0 = s * 32;
        #pragma unroll
        for (int i = 0; i < 4; i++) {
            int gr = rowBase + aRow[i];
            pa[i] = (gr < Mvalid)
                  ? *reinterpret_cast<const float4*>(A + (size_t)gr * K + k0 + aC4[i] * 4)
                  : make_float4(0.f, 0.f, 0.f, 0.f);
        }
    };
    auto storeA = [&](int b) {
        #pragma unroll
        for (int i = 0; i < 4; i++) {
            uint32_t h01, l01, h23, l23;
            split_pack2(pa[i].x, pa[i].y, h01, l01);
            split_pack2(pa[i].z, pa[i].w, h23, l23);
            uint32_t off = aRow[i] * 80 + aC4[i] * 8;
            *reinterpret_cast<uint2*>(smem_raw + off + b * STG) = make_uint2(h01, h23);
            *reinterpret_cast<uint2*>(smem_raw + off + b * STG + OFF_AL) = make_uint2(l01, l23);
        }
    };
    // B loader: BN rows x 4 16B chunks = BN*4 slots; BN/64 per thread
    auto issueB = [&](int s, int b) {
        const int k0 = s * 32;
        const uint32_t sb = smem_b + b * STG;
        #pragma unroll
        for (int i = 0; i < BN / 64; i++) {
            int idx = tid + i * 256;
            int n = idx >> 2, c = idx & 3;
            size_t g = (size_t)(colBase + n) * K + k0 + c * 8;
            uint32_t off = n * 80 + c * 16;
            cp16(sb + OFF_BH + off, Bhi + g);
            cp16(sb + OFF_BL + off, Blo + g);
        }
        asm volatile("cp.async.commit_group;" ::: "memory");
    };

    loadA(0);
    issueB(0, 0);

    for (int s = 0; s < nStages; s++) {
        const int b = s & 1;
        storeA(b);
        if (s + 1 < nStages) {
            loadA(s + 1);
            issueB(s + 1, b ^ 1);
            asm volatile("cp.async.wait_group 1;" ::: "memory");
        } else {
            asm volatile("cp.async.wait_group 0;" ::: "memory");
        }
        __syncthreads();

        const uint32_t sAh = smem_b + b * STG;
        const uint32_t sAl = sAh + OFF_AL;
        const uint32_t sBh = sAh + OFF_BH;
        const uint32_t sBl = sAh + OFF_BL;

        // ldmatrix lane address components
        const int aLRow = lane & 15;
        const int aKoff = (lane >> 4) * 8;
        const int bLN   = ((lane >> 4) << 3) + (lane & 7);
        const int bKoff = ((lane >> 3) & 1) * 8;

        #pragma unroll
        for (int kk = 0; kk < 2; kk++) {
            const int kb = kk * 16;
            uint32_t ah[2][4], al[2][4];
            #pragma unroll
            for (int mt = 0; mt < 2; mt++) {
                int r = (wm * 2 + mt) * 16 + aLRow;
                uint32_t ad = sAh + r * 80 + (kb + aKoff) * 2;
                ldsm4(ah[mt][0], ah[mt][1], ah[mt][2], ah[mt][3], ad);
                ad = sAl + r * 80 + (kb + aKoff) * 2;
                ldsm4(al[mt][0], al[mt][1], al[mt][2], al[mt][3], ad);
            }
            uint32_t bh[NP][4], bl[NP][4];
            #pragma unroll
            for (int p = 0; p < NP; p++) {
                int n = wn * WN + p * 16 + bLN;
                uint32_t bd = sBh + n * 80 + (kb + bKoff) * 2;
                ldsm4(bh[p][0], bh[p][1], bh[p][2], bh[p][3], bd);
                bd = sBl + n * 80 + (kb + bKoff) * 2;
                ldsm4(bl[p][0], bl[p][1], bl[p][2], bl[p][3], bd);
            }
            #pragma unroll
            for (int mt = 0; mt < 2; mt++) {
                #pragma unroll
                for (int nt = 0; nt < NT; nt++) {
                    float* d = acc[mt][nt];
                    int p = nt >> 1, q = (nt & 1) * 2;
                    uint32_t b0h = bh[p][q], b1h = bh[p][q + 1];
                    uint32_t b0l = bl[p][q], b1l = bl[p][q + 1];
                    mma_bf16(d[0], d[1], d[2], d[3],
                             ah[mt][0], ah[mt][1], ah[mt][2], ah[mt][3], b0h, b1h);
                    mma_bf16(d[0], d[1], d[2], d[3],
                             al[mt][0], al[mt][1], al[mt][2], al[mt][3], b0h, b1h);
                    mma_bf16(d[0], d[1], d[2], d[3],
                             ah[mt][0], ah[mt][1], ah[mt][2], ah[mt][3], b0l, b1l);
                }
            }
        }
        __syncthreads();
    }

    // epilogue
    #pragma unroll
    for (int mt = 0; mt < 2; mt++) {
        int r0 = rowBase + wm * 32 + mt * 16 + (lane >> 2);
        int r1 = r0 + 8;
        float rs0 = rowscale ? rowscale[r0] : 1.f;
        float rs1 = rowscale ? rowscale[r1] : 1.f;
        #pragma unroll
        for (int nt = 0; nt < NT; nt++) {
            int c0 = colBase + wn * WN + nt * 8 + (lane & 3) * 2;
            float b0 = (bias && c0 < Nout)     ? bias[c0]     : 0.f;
            float b1 = (bias && c0 + 1 < Nout) ? bias[c0 + 1] : 0.f;
            float v00 = acc[mt][nt][0] * rs0 + b0;
            float v01 = acc[mt][nt][1] * rs0 + b1;
            float v10 = acc[mt][nt][2] * rs1 + b0;
            float v11 = acc[mt][nt][3] * rs1 + b1;
            if (Chalf) {
                *reinterpret_cast<__half2*>(Chalf + (size_t)r0 * ldC + c0) = __floats2half2_rn(v00, v01);
                *reinterpret_cast<__half2*>(Chalf + (size_t)r1 * ldC + c0) = __floats2half2_rn(v10, v11);
            } else if (c0 + 1 < Nout) {
                if (r0 < Mout) *reinterpret_cast<float2*>(C + (size_t)r0 * ldC + c0) = make_float2(v00, v01);
                if (r1 < Mout) *reinterpret_cast<float2*>(C + (size_t)r1 * ldC + c0) = make_float2(v10, v11);
            } else if (c0 < Nout) {
                if (r0 < Mout) C[(size_t)r0 * ldC + c0] = v00;
                if (r1 < Mout) C[(size_t)r1 * ldC + c0] = v10;
            }
        }
    }
}

#define SMEM128 (2 * (20480 + 2 * 128 * 80))   // 81920
#define SMEM64  (2 * (20480 + 2 * 64 * 80))    // 61440

// ---------------------------------------------------------------------------
extern "C" void kernel_launch(void* const* d_in, const int* in_sizes, int n_in,
                              void* d_out, int out_size)
{
    const float* n_feats = (const float*)d_in[0];
    const int*   src     = (const int*)  d_in[1];
    const int*   dst     = (const int*)  d_in[2];
    const float* Wp      = (const float*)d_in[3];
    const float* bp      = (const float*)d_in[4];
    const float* W1      = (const float*)d_in[5];
    const float* b1      = (const float*)d_in[6];
    const float* W2      = (const float*)d_in[7];
    const float* b2      = (const float*)d_in[8];
    const float* Wc      = (const float*)d_in[9];
    const float* bc      = (const float*)d_in[10];
    float* out = (float*)d_out;
    int E = in_sizes[1];

    float *X, *degout;
    __half *Hh;
    __nv_bfloat16 *Wphi, *Wplo, *W1hi, *W1lo, *W2hi, *W2lo, *Wchi, *Wclo;
    cudaGetSymbolAddress((void**)&X, g_X);
    cudaGetSymbolAddress((void**)&Hh, g_Hh);
    cudaGetSymbolAddress((void**)&degout, g_degout);
    cudaGetSymbolAddress((void**)&Wphi, gWp_hi); cudaGetSymbolAddress((void**)&Wplo, gWp_lo);
    cudaGetSymbolAddress((void**)&W1hi, gW1_hi); cudaGetSymbolAddress((void**)&W1lo, gW1_lo);
    cudaGetSymbolAddress((void**)&W2hi, gW2_hi); cudaGetSymbolAddress((void**)&W2lo, gW2_lo);
    cudaGetSymbolAddress((void**)&Wchi, gWc_hi); cudaGetSymbolAddress((void**)&Wclo, gWc_lo);

    // one-time host-side setup (no device allocation)
    static bool init_done = false;
    static cudaStream_t s2 = nullptr;
    static cudaEvent_t evFork, evDeg, evCsr, evW;
    if (!init_done) {
        cudaFuncSetAttribute(mma_gemm_kernel<128>, cudaFuncAttributeMaxDynamicSharedMemorySize,
                             SMEM128);
        cudaFuncSetAttribute(mma_gemm_kernel<64>, cudaFuncAttributeMaxDynamicSharedMemorySize,
                             SMEM64);
        cudaStreamCreateWithFlags(&s2, cudaStreamNonBlocking);
        cudaEventCreateWithFlags(&evFork, cudaEventDisableTiming);
        cudaEventCreateWithFlags(&evDeg,  cudaEventDisableTiming);
        cudaEventCreateWithFlags(&evCsr,  cudaEventDisableTiming);
        cudaEventCreateWithFlags(&evW,    cudaEventDisableTiming);
        init_done = true;
    }

    const int T = 256;
    int nodeBlocks = (NPAD + T - 1) / T;
    int edgeBlocks = (E + T - 1) / T;
    int aggBlocks  = (NPAD + 7) / 8;

    dim3 gH(1, NPAD / 128);    // BN=128 GEMMs
    dim3 gC(1, NPAD / 128);    // BN=64 classifier

    // ---- fork: CSR + degree + layer-weight presplit chain on s2 ----
    cudaEventRecord(evFork, 0);
    cudaStreamWaitEvent(s2, evFork, 0);

    presplit_W12c_kernel<<<(40960 + T - 1) / T, T, 0, s2>>>(W1, W2, Wc);
    cudaEventRecord(evW, s2);
    zero_cnt_kernel<<<nodeBlocks, T, 0, s2>>>();
    count_kernel<<<edgeBlocks, T, 0, s2>>>(src, dst, E);
    rsqrt_kernel<<<nodeBlocks, T, 0, s2>>>();
    cudaEventRecord(evDeg, s2);
    scan_phaseA<<<SCAN_B, T, 0, s2>>>();
    scan_phaseB<<<1, T, 0, s2>>>();
    scan_phaseC<<<SCAN_B, T, 0, s2>>>();
    scatter_kernel<<<edgeBlocks, T, 0, s2>>>(src, dst, E);
    cudaEventRecord(evCsr, s2);

    // stream 0: only Wp presplit, then projection GEMM immediately
    presplit_Wt_kernel<<<(H_DIM * F_DIM + T - 1) / T, T>>>(Wp, Wphi, Wplo, F_DIM, H_DIM, H_DIM);

    // projection: X = n_feats @ Wp + bp  (fp32 out)
    mma_gemm_kernel<128><<<gH, T, SMEM128>>>(n_feats, N_NODES, Wphi, Wplo, F_DIM,
                                             X, nullptr, H_DIM, NPAD, H_DIM, bp, nullptr);

    // ---- GCN layer 1 (GEMM needs degout + W1 split; agg needs CSR) ----
    cudaStreamWaitEvent(0, evDeg, 0);
    cudaStreamWaitEvent(0, evW, 0);
    mma_gemm_kernel<128><<<gH, T, SMEM128>>>(X, NPAD, W1hi, W1lo, H_DIM,
                                             nullptr, Hh, H_DIM, NPAD, H_DIM, nullptr, degout);
    cudaStreamWaitEvent(0, evCsr, 0);
    csr_agg_kernel<<<aggBlocks, T>>>(b1);

    // ---- GCN layer 2 ----
    mma_gemm_kernel<128><<<gH, T, SMEM128>>>(X, NPAD, W2hi, W2lo, H_DIM,
                                             nullptr, Hh, H_DIM, NPAD, H_DIM, nullptr, degout);
    csr_agg_kernel<<<aggBlocks, T>>>(b2);

    // classifier: out = X @ Wc + bc  (fp32 out)
    mma_gemm_kernel<64><<<gC, T, SMEM64>>>(X, NPAD, Wchi, Wclo, H_DIM,
                                           out, nullptr, C_DIM, N_NODES, C_DIM, bc, nullptr);
}

// round 14
// speedup vs baseline: 1.5414x; 1.5414x over previous
#include <cuda_runtime.h>
#include <cuda_bf16.h>
#include <cuda_fp16.h>
#include <cstdint>

#define N_NODES 50000
#define NPAD    50048            // 391 * 128
#define H_DIM   128
#define F_DIM   256
#define C_DIM   40
#define CPAD    64
#define E_CAP   800000
#define SCAN_B  196              // ceil(NPAD / 256)

// ---------------------------------------------------------------------------
// Global scratch (static device globals)
// ---------------------------------------------------------------------------
__device__ float  g_X[NPAD * H_DIM];     // activations (plain fp32)
__device__ __half g_Hh[NPAD * H_DIM];    // x @ W, row-scaled, fp16 messages
__device__ float  g_degout[NPAD];        // rsqrt(max(deg_out,1))
__device__ float  g_degin [NPAD];
__device__ int    g_cntin[NPAD], g_cntout[NPAD], g_cnt2[NPAD];
__device__ int    g_rowstart[NPAD + 1];
__device__ int    g_srcsorted[E_CAP];
__device__ int    g_blocksum[SCAN_B];
__device__ int    g_blockoff[SCAN_B];
// weights pre-split to bf16 hi/lo, TRANSPOSED to [N x K] row-major
__device__ __nv_bfloat16 gWp_hi[H_DIM * F_DIM], gWp_lo[H_DIM * F_DIM];
__device__ __nv_bfloat16 gW1_hi[H_DIM * H_DIM], gW1_lo[H_DIM * H_DIM];
__device__ __nv_bfloat16 gW2_hi[H_DIM * H_DIM], gW2_lo[H_DIM * H_DIM];
__device__ __nv_bfloat16 gWc_hi[CPAD  * H_DIM], gWc_lo[CPAD  * H_DIM];

// ---------------------------------------------------------------------------
// CSR build + degree kernels
// ---------------------------------------------------------------------------
__global__ void zero_cnt_kernel() {
    int i = blockIdx.x * blockDim.x + threadIdx.x;
    if (i < NPAD) { g_cntin[i] = 0; g_cntout[i] = 0; g_cnt2[i] = 0; }
}

__global__ void count_kernel(const int* __restrict__ src, const int* __restrict__ dst, int E) {
    int i = blockIdx.x * blockDim.x + threadIdx.x;
    if (i < E) {
        atomicAdd(&g_cntout[src[i]], 1);
        atomicAdd(&g_cntin[dst[i]], 1);
    }
}

// ---- 3-phase multi-block exclusive scan of g_cntin -> g_rowstart ----------
// phase A also computes rsqrt(deg) (fused former rsqrt_kernel)
__global__ void scan_phaseA() {
    int t = threadIdx.x;
    int idx = blockIdx.x * 256 + t;
    int v = (idx < NPAD) ? g_cntin[idx] : 0;
    if (idx < NPAD) {
        g_degin[idx]  = rsqrtf((float)max(v, 1));
        g_degout[idx] = rsqrtf((float)max(g_cntout[idx], 1));
    }
    int r = v;
    #pragma unroll
    for (int o = 16; o; o >>= 1) r += __shfl_down_sync(0xffffffffu, r, o);
    __shared__ int ws[8];
    if ((t & 31) == 0) ws[t >> 5] = r;
    __syncthreads();
    if (t < 8) {
        int s = ws[t];
        #pragma unroll
        for (int o = 4; o; o >>= 1) s += __shfl_down_sync(0xffu, s, o);
        if (t == 0) g_blocksum[blockIdx.x] = s;
    }
}

__global__ void scan_phaseB() {
    int t = threadIdx.x;
    int lane = t & 31, w = t >> 5;
    int v = (t < SCAN_B) ? g_blocksum[t] : 0;
    int x = v;
    #pragma unroll
    for (int o = 1; o < 32; o <<= 1) {
        int y = __shfl_up_sync(0xffffffffu, x, o);
        if (lane >= o) x += y;
    }
    __shared__ int ws[8];
    if (lane == 31) ws[w] = x;
    __syncthreads();
    if (t == 0) {
        int s = 0;
        #pragma unroll
        for (int i = 0; i < 8; i++) { int tmp = ws[i]; ws[i] = s; s += tmp; }
    }
    __syncthreads();
    int incl = x + ws[w];
    if (t < SCAN_B) {
        g_blockoff[t] = incl - v;
        if (t == SCAN_B - 1) g_rowstart[NPAD] = incl;
    }
}

__global__ void scan_phaseC() {
    int t = threadIdx.x;
    int idx = blockIdx.x * 256 + t;
    int lane = t & 31, w = t >> 5;
    int v = (idx < NPAD) ? g_cntin[idx] : 0;
    int x = v;
    #pragma unroll
    for (int o = 1; o < 32; o <<= 1) {
        int y = __shfl_up_sync(0xffffffffu, x, o);
        if (lane >= o) x += y;
    }
    __shared__ int ws[8];
    if (lane == 31) ws[w] = x;
    __syncthreads();
    if (t == 0) {
        int s = 0;
        #pragma unroll
        for (int i = 0; i < 8; i++) { int tmp = ws[i]; ws[i] = s; s += tmp; }
    }
    __syncthreads();
    int excl = x - v + ws[w] + g_blockoff[blockIdx.x];
    if (idx < NPAD) g_rowstart[idx] = excl;
}

__global__ void scatter_kernel(const int* __restrict__ src, const int* __restrict__ dst, int E) {
    int i = blockIdx.x * blockDim.x + threadIdx.x;
    if (i < E) {
        int d = dst[i];
        int pos = g_rowstart[d] + atomicAdd(&g_cnt2[d], 1);
        g_srcsorted[pos] = src[i];
    }
}

// ---------------------------------------------------------------------------
// CSR aggregate + finalize: one warp per dst node, fp16 messages.
// ---------------------------------------------------------------------------
__global__ void csr_agg_kernel(const float* __restrict__ bias) {
    int warp = (blockIdx.x * blockDim.x + threadIdx.x) >> 5;
    int lane = threadIdx.x & 31;
    if (warp >= NPAD) return;
    int beg = g_rowstart[warp];
    int end = g_rowstart[warp + 1];
    float4 acc = make_float4(0.f, 0.f, 0.f, 0.f);
    const uint2* Hv = reinterpret_cast<const uint2*>(g_Hh);

    auto addrow = [&](int s) {
        uint2 u = Hv[s * 32 + lane];
        __half2 p0 = *reinterpret_cast<__half2*>(&u.x);
        __half2 p1 = *reinterpret_cast<__half2*>(&u.y);
        float2 f0 = __half22float2(p0);
        float2 f1 = __half22float2(p1);
        acc.x += f0.x; acc.y += f0.y; acc.z += f1.x; acc.w += f1.y;
    };

    int e = beg;
    for (; e + 7 < end; e += 8) {
        int s0 = g_srcsorted[e],   s1 = g_srcsorted[e+1], s2 = g_srcsorted[e+2], s3 = g_srcsorted[e+3];
        int s4 = g_srcsorted[e+4], s5 = g_srcsorted[e+5], s6 = g_srcsorted[e+6], s7 = g_srcsorted[e+7];
        addrow(s0); addrow(s1); addrow(s2); addrow(s3);
        addrow(s4); addrow(s5); addrow(s6); addrow(s7);
    }
    for (; e < end; e++) addrow(g_srcsorted[e]);

    float rs = g_degin[warp];
    float4 b = reinterpret_cast<const float4*>(bias)[lane];
    float4 x;
    x.x = fmaxf(acc.x * rs + b.x, 0.f);
    x.y = fmaxf(acc.y * rs + b.y, 0.f);
    x.z = fmaxf(acc.z * rs + b.z, 0.f);
    x.w = fmaxf(acc.w * rs + b.w, 0.f);
    reinterpret_cast<float4*>(g_X)[warp * 32 + lane] = x;
}

// ---------------------------------------------------------------------------
// weight pre-split: W[K x N] -> bf16 hi/lo [Npad x K] (transposed, padded)
// ---------------------------------------------------------------------------
__device__ __forceinline__ void wsplit_one(const float* W, __nv_bfloat16* hi, __nv_bfloat16* lo,
                                           int K, int N, int Npad, int i) {
    int n = i / K, k = i - n * K;
    float v = (n < N) ? W[(size_t)k * N + n] : 0.f;
    __nv_bfloat16 h = __float2bfloat16_rn(v);
    float r = v - __bfloat162float(h);
    hi[i] = h;
    lo[i] = __float2bfloat16_rn(r);
}

__global__ void presplit_Wt_kernel(const float* __restrict__ W,
                                   __nv_bfloat16* __restrict__ hi,
                                   __nv_bfloat16* __restrict__ lo,
                                   int K, int N, int Npad) {
    int i = blockIdx.x * blockDim.x + threadIdx.x;
    if (i >= Npad * K) return;
    wsplit_one(W, hi, lo, K, N, Npad, i);
}

// merged presplit for W1, W2, Wc in one launch
__global__ void presplit_W12c_kernel(const float* __restrict__ W1,
                                     const float* __restrict__ W2,
                                     const float* __restrict__ Wc) {
    int i = blockIdx.x * blockDim.x + threadIdx.x;
    if (i < 16384) {
        wsplit_one(W1, gW1_hi, gW1_lo, H_DIM, H_DIM, H_DIM, i);
    } else if (i < 32768) {
        wsplit_one(W2, gW2_hi, gW2_lo, H_DIM, H_DIM, H_DIM, i - 16384);
    } else if (i < 40960) {
        wsplit_one(Wc, gWc_hi, gWc_lo, H_DIM, C_DIM, CPAD, i - 32768);
    }
}

// ---------------------------------------------------------------------------
// split-BF16 GEMM (3 products: hh + lh + hl): C[M,N] = A[M,K] @ Wt[N x K]
// BM=128, BN=64, BK=32, 256 threads (8 warps: 4m x 2n), warp tile 32x32.
// A: LDG fp32 -> split to bf16 hi/lo in regs -> STS -> ldmatrix.b16
// B: cp.async pre-split bf16 tiles -> ldmatrix.b16
// mma.sync.m16n8k16.bf16, fp32 accum.
// ---------------------------------------------------------------------------
#define OFF_AH   0
#define OFF_AL   10240                    // 128 * 80
#define OFF_BH   20480
#define OFF_BL   25600                    // + 64 * 80
#define STG_BYTES 30720
#define SMEM_TOT (2 * STG_BYTES)          // 61440

__device__ __forceinline__ void cp16(uint32_t saddr, const void* g) {
    asm volatile("cp.async.ca.shared.global [%0], [%1], 16;" :: "r"(saddr), "l"(g) : "memory");
}

__device__ __forceinline__ void ldsm4(uint32_t& r0, uint32_t& r1, uint32_t& r2, uint32_t& r3,
                                      uint32_t saddr) {
    asm volatile("ldmatrix.sync.aligned.m8n8.x4.shared.b16 {%0,%1,%2,%3}, [%4];"
                 : "=r"(r0), "=r"(r1), "=r"(r2), "=r"(r3) : "r"(saddr));
}

__device__ __forceinline__ void mma_bf16(
    float& d0, float& d1, float& d2, float& d3,
    uint32_t a0, uint32_t a1, uint32_t a2, uint32_t a3,
    uint32_t b0, uint32_t b1)
{
    asm volatile(
        "mma.sync.aligned.m16n8k16.row.col.f32.bf16.bf16.f32 "
        "{%0,%1,%2,%3}, {%4,%5,%6,%7}, {%8,%9}, {%0,%1,%2,%3};"
        : "+f"(d0), "+f"(d1), "+f"(d2), "+f"(d3)
        : "r"(a0), "r"(a1), "r"(a2), "r"(a3), "r"(b0), "r"(b1));
}

// pack two floats' bf16 hi parts / lo parts
__device__ __forceinline__ void split_pack2(float x, float y, uint32_t& hi2, uint32_t& lo2) {
    __nv_bfloat162 h = __floats2bfloat162_rn(x, y);
    float rx = x - __bfloat162float(__low2bfloat16(h));
    float ry = y - __bfloat162float(__high2bfloat16(h));
    __nv_bfloat162 l = __floats2bfloat162_rn(rx, ry);
    hi2 = *reinterpret_cast<uint32_t*>(&h);
    lo2 = *reinterpret_cast<uint32_t*>(&l);
}

__global__ __launch_bounds__(256) void mma_gemm_kernel(
    const float* __restrict__ A, int Mvalid,
    const __nv_bfloat16* __restrict__ Bhi, const __nv_bfloat16* __restrict__ Blo, int K,
    float* __restrict__ C, __half* __restrict__ Chalf, int ldC, int Mout, int Nout,
    const float* __restrict__ bias, const float* __restrict__ rowscale)
{
    extern __shared__ uint8_t smem_raw[];
    const uint32_t smem_b = (uint32_t)__cvta_generic_to_shared(smem_raw);

    const int tid  = threadIdx.x;
    const int lane = tid & 31;
    const int warp = tid >> 5;
    const int wm   = warp >> 1;          // 0..3
    const int wn   = warp & 1;           // 0..1
    const int rowBase = blockIdx.y * 128;
    const int colBase = blockIdx.x * 64;
    const int nStages = K >> 5;

    float acc[2][4][4];
    #pragma unroll
    for (int i = 0; i < 2; i++)
        #pragma unroll
        for (int j = 0; j < 4; j++)
            #pragma unroll
            for (int l = 0; l < 4; l++) acc[i][j][l] = 0.f;

    // A loader slots: 4 float4/thread; row = idx>>3, c4 = idx&7 (32 floats/row)
    int aRow[4], aC4[4];
    #pragma unroll
    for (int i = 0; i < 4; i++) {
        int idx = tid + i * 256;
        aRow[i] = idx >> 3;
        aC4[i]  = idx & 7;
    }
    // B loader slot: 1 per thread: n = tid>>2, c16 = tid&3
    const int bN = tid >> 2, bC = tid & 3;

    float4 pa[4];
    auto loadA = [&](int s) {
        const int k0 = s * 32;
        #pragma unroll
        for (int i = 0; i < 4; i++) {
            int gr = rowBase + aRow[i];
            pa[i] = (gr < Mvalid)
                  ? *reinterpret_cast<const float4*>(A + (size_t)gr * K + k0 + aC4[i] * 4)
                  : make_float4(0.f, 0.f, 0.f, 0.f);
        }
    };
    auto storeA = [&](int b) {
        #pragma unroll
        for (int i = 0; i < 4; i++) {
            uint32_t h01, l01, h23, l23;
            split_pack2(pa[i].x, pa[i].y, h01, l01);
            split_pack2(pa[i].z, pa[i].w, h23, l23);
            uint32_t off = aRow[i] * 80 + aC4[i] * 8;
            *reinterpret_cast<uint2*>(smem_raw + off + b * STG_BYTES + OFF_AH) = make_uint2(h01, h23);
            *reinterpret_cast<uint2*>(smem_raw + off + b * STG_BYTES + OFF_AL) = make_uint2(l01, l23);
        }
    };
    auto issueB = [&](int s, int b) {
        const int k0 = s * 32;
        const uint32_t sb = smem_b + b * STG_BYTES;
        size_t g = (size_t)(colBase + bN) * K + k0 + bC * 8;
        uint32_t off = bN * 80 + bC * 16;
        cp16(sb + OFF_BH + off, Bhi + g);
        cp16(sb + OFF_BL + off, Blo + g);
        asm volatile("cp.async.commit_group;" ::: "memory");
    };

    loadA(0);
    issueB(0, 0);

    for (int s = 0; s < nStages; s++) {
        const int b = s & 1;
        storeA(b);
        if (s + 1 < nStages) {
            loadA(s + 1);
            issueB(s + 1, b ^ 1);
            asm volatile("cp.async.wait_group 1;" ::: "memory");
        } else {
            asm volatile("cp.async.wait_group 0;" ::: "memory");
        }
        __syncthreads();

        const uint32_t sAh = smem_b + b * STG_BYTES + OFF_AH;
        const uint32_t sAl = smem_b + b * STG_BYTES + OFF_AL;
        const uint32_t sBh = smem_b + b * STG_BYTES + OFF_BH;
        const uint32_t sBl = smem_b + b * STG_BYTES + OFF_BL;

        // ldmatrix lane address components
        const int aLRow = lane & 15;               // row within 16-row tile
        const int aKoff = (lane >> 4) * 8;         // +8 k for mats 2,3
        const int bLN   = ((lane >> 4) << 3) + (lane & 7);  // n within 16-col pair
        const int bKoff = ((lane >> 3) & 1) * 8;   // +8 k for mats 1,3

        #pragma unroll
        for (int kk = 0; kk < 2; kk++) {
            const int kb = kk * 16;
            uint32_t ah[2][4], al[2][4];
            #pragma unroll
            for (int mt = 0; mt < 2; mt++) {
                int r = (wm * 2 + mt) * 16 + aLRow;
                uint32_t ad = sAh + r * 80 + (kb + aKoff) * 2;
                ldsm4(ah[mt][0], ah[mt][1], ah[mt][2], ah[mt][3], ad);
                ad = sAl + r * 80 + (kb + aKoff) * 2;
                ldsm4(al[mt][0], al[mt][1], al[mt][2], al[mt][3], ad);
            }
            uint32_t bh[2][4], bl[2][4];
            #pragma unroll
            for (int p = 0; p < 2; p++) {
                int n = wn * 32 + p * 16 + bLN;
                uint32_t bd = sBh + n * 80 + (kb + bKoff) * 2;
                ldsm4(bh[p][0], bh[p][1], bh[p][2], bh[p][3], bd);
                bd = sBl + n * 80 + (kb + bKoff) * 2;
                ldsm4(bl[p][0], bl[p][1], bl[p][2], bl[p][3], bd);
            }
            #pragma unroll
            for (int mt = 0; mt < 2; mt++) {
                #pragma unroll
                for (int nt = 0; nt < 4; nt++) {
                    float* d = acc[mt][nt];
                    int p = nt >> 1, q = (nt & 1) * 2;
                    uint32_t b0h = bh[p][q], b1h = bh[p][q + 1];
                    uint32_t b0l = bl[p][q], b1l = bl[p][q + 1];
                    mma_bf16(d[0], d[1], d[2], d[3],
                             ah[mt][0], ah[mt][1], ah[mt][2], ah[mt][3], b0h, b1h);
                    mma_bf16(d[0], d[1], d[2], d[3],
                             al[mt][0], al[mt][1], al[mt][2], al[mt][3], b0h, b1h);
                    mma_bf16(d[0], d[1], d[2], d[3],
                             ah[mt][0], ah[mt][1], ah[mt][2], ah[mt][3], b0l, b1l);
                }
            }
        }
        __syncthreads();
    }

    // epilogue
    #pragma unroll
    for (int mt = 0; mt < 2; mt++) {
        int r0 = rowBase + wm * 32 + mt * 16 + (lane >> 2);
        int r1 = r0 + 8;
        float rs0 = rowscale ? rowscale[r0] : 1.f;
        float rs1 = rowscale ? rowscale[r1] : 1.f;
        #pragma unroll
        for (int nt = 0; nt < 4; nt++) {
            int c0 = colBase + wn * 32 + nt * 8 + (lane & 3) * 2;
            float b0 = (bias && c0 < Nout)     ? bias[c0]     : 0.f;
            float b1 = (bias && c0 + 1 < Nout) ? bias[c0 + 1] : 0.f;
            float v00 = acc[mt][nt][0] * rs0 + b0;
            float v01 = acc[mt][nt][1] * rs0 + b1;
            float v10 = acc[mt][nt][2] * rs1 + b0;
            float v11 = acc[mt][nt][3] * rs1 + b1;
            if (Chalf) {
                *reinterpret_cast<__half2*>(Chalf + (size_t)r0 * ldC + c0) = __floats2half2_rn(v00, v01);
                *reinterpret_cast<__half2*>(Chalf + (size_t)r1 * ldC + c0) = __floats2half2_rn(v10, v11);
            } else if (c0 + 1 < Nout) {
                if (r0 < Mout) *reinterpret_cast<float2*>(C + (size_t)r0 * ldC + c0) = make_float2(v00, v01);
                if (r1 < Mout) *reinterpret_cast<float2*>(C + (size_t)r1 * ldC + c0) = make_float2(v10, v11);
            } else if (c0 < Nout) {
                if (r0 < Mout) C[(size_t)r0 * ldC + c0] = v00;
                if (r1 < Mout) C[(size_t)r1 * ldC + c0] = v10;
            }
        }
    }
}

// ---------------------------------------------------------------------------
extern "C" void kernel_launch(void* const* d_in, const int* in_sizes, int n_in,
                              void* d_out, int out_size)
{
    const float* n_feats = (const float*)d_in[0];
    const int*   src     = (const int*)  d_in[1];
    const int*   dst     = (const int*)  d_in[2];
    const float* Wp      = (const float*)d_in[3];
    const float* bp      = (const float*)d_in[4];
    const float* W1      = (const float*)d_in[5];
    const float* b1      = (const float*)d_in[6];
    const float* W2      = (const float*)d_in[7];
    const float* b2      = (const float*)d_in[8];
    const float* Wc      = (const float*)d_in[9];
    const float* bc      = (const float*)d_in[10];
    float* out = (float*)d_out;
    int E = in_sizes[1];

    float *X, *degout;
    __half *Hh;
    __nv_bfloat16 *Wphi, *Wplo, *W1hi, *W1lo, *W2hi, *W2lo, *Wchi, *Wclo;
    cudaGetSymbolAddress((void**)&X, g_X);
    cudaGetSymbolAddress((void**)&Hh, g_Hh);
    cudaGetSymbolAddress((void**)&degout, g_degout);
    cudaGetSymbolAddress((void**)&Wphi, gWp_hi); cudaGetSymbolAddress((void**)&Wplo, gWp_lo);
    cudaGetSymbolAddress((void**)&W1hi, gW1_hi); cudaGetSymbolAddress((void**)&W1lo, gW1_lo);
    cudaGetSymbolAddress((void**)&W2hi, gW2_hi); cudaGetSymbolAddress((void**)&W2lo, gW2_lo);
    cudaGetSymbolAddress((void**)&Wchi, gWc_hi); cudaGetSymbolAddress((void**)&Wclo, gWc_lo);

    // one-time host-side setup (no device allocation)
    static bool init_done = false;
    static cudaStream_t s2 = nullptr;
    static cudaEvent_t evFork, evDeg, evCsr, evW;
    if (!init_done) {
        cudaFuncSetAttribute(mma_gemm_kernel, cudaFuncAttributeMaxDynamicSharedMemorySize,
                             SMEM_TOT);
        cudaStreamCreateWithFlags(&s2, cudaStreamNonBlocking);
        cudaEventCreateWithFlags(&evFork, cudaEventDisableTiming);
        cudaEventCreateWithFlags(&evDeg,  cudaEventDisableTiming);
        cudaEventCreateWithFlags(&evCsr,  cudaEventDisableTiming);
        cudaEventCreateWithFlags(&evW,    cudaEventDisableTiming);
        init_done = true;
    }

    const int T = 256;
    int nodeBlocks = (NPAD + T - 1) / T;
    int edgeBlocks = (E + T - 1) / T;
    int aggBlocks  = (NPAD + 7) / 8;

    dim3 gH(2, NPAD / 128);
    dim3 gC(1, NPAD / 128);

    // ---- fork: CSR + degree + layer-weight presplit chain on s2 ----
    cudaEventRecord(evFork, 0);
    cudaStreamWaitEvent(s2, evFork, 0);

    presplit_W12c_kernel<<<(40960 + T - 1) / T, T, 0, s2>>>(W1, W2, Wc);
    cudaEventRecord(evW, s2);
    zero_cnt_kernel<<<nodeBlocks, T, 0, s2>>>();
    count_kernel<<<edgeBlocks, T, 0, s2>>>(src, dst, E);
    scan_phaseA<<<SCAN_B, T, 0, s2>>>();      // also computes rsqrt(deg)
    cudaEventRecord(evDeg, s2);
    scan_phaseB<<<1, T, 0, s2>>>();
    scan_phaseC<<<SCAN_B, T, 0, s2>>>();
    scatter_kernel<<<edgeBlocks, T, 0, s2>>>(src, dst, E);
    cudaEventRecord(evCsr, s2);

    // stream 0: only Wp presplit, then projection GEMM immediately
    presplit_Wt_kernel<<<(H_DIM * F_DIM + T - 1) / T, T>>>(Wp, Wphi, Wplo, F_DIM, H_DIM, H_DIM);

    // projection: X = n_feats @ Wp + bp  (fp32 out)
    mma_gemm_kernel<<<gH, T, SMEM_TOT>>>(n_feats, N_NODES, Wphi, Wplo, F_DIM,
                                         X, nullptr, H_DIM, NPAD, H_DIM, bp, nullptr);

    // ---- GCN layer 1 (GEMM needs degout + W1 split; agg needs CSR) ----
    cudaStreamWaitEvent(0, evDeg, 0);
    cudaStreamWaitEvent(0, evW, 0);
    mma_gemm_kernel<<<gH, T, SMEM_TOT>>>(X, NPAD, W1hi, W1lo, H_DIM,
                                         nullptr, Hh, H_DIM, NPAD, H_DIM, nullptr, degout);
    cudaStreamWaitEvent(0, evCsr, 0);
    csr_agg_kernel<<<aggBlocks, T>>>(b1);

    // ---- GCN layer 2 ----
    mma_gemm_kernel<<<gH, T, SMEM_TOT>>>(X, NPAD, W2hi, W2lo, H_DIM,
                                         nullptr, Hh, H_DIM, NPAD, H_DIM, nullptr, degout);
    csr_agg_kernel<<<aggBlocks, T>>>(b2);

    // classifier: out = X @ Wc + bc  (fp32 out)
    mma_gemm_kernel<<<gC, T, SMEM_TOT>>>(X, NPAD, Wchi, Wclo, H_DIM,
                                         out, nullptr, C_DIM, N_NODES, C_DIM, bc, nullptr);
}

// round 15
// speedup vs baseline: 1.6211x; 1.0517x over previous
#include <cuda_runtime.h>
#include <cuda_bf16.h>
#include <cuda_fp16.h>
#include <cstdint>

#define N_NODES 50000
#define NPAD    50048            // 391 * 128
#define H_DIM   128
#define F_DIM   256
#define C_DIM   40
#define CPAD    64
#define E_CAP   800000
#define SCAN_B  196              // ceil(NPAD / 256)

// ---------------------------------------------------------------------------
// Global scratch (static device globals)
// ---------------------------------------------------------------------------
__device__ float  g_X[NPAD * H_DIM];     // activations (plain fp32)
__device__ __half g_Hh[NPAD * H_DIM];    // messages (fp16)
__device__ float  g_degout[NPAD];        // rsqrt(max(deg_out,1))
__device__ float  g_degin [NPAD];
__device__ int    g_cntin[NPAD], g_cntout[NPAD], g_cnt2[NPAD];
__device__ int    g_rowstart[NPAD + 1];
__device__ int    g_srcsorted[E_CAP];
__device__ int    g_blocksum[SCAN_B];
__device__ int    g_blockoff[SCAN_B];
__device__ float  g_bfused[H_DIM];       // bp @ W1
// fused weight Wp@W1, split bf16, TRANSPOSED [n (128) x k (256)]
__device__ __nv_bfloat16 gWf_hi[H_DIM * F_DIM], gWf_lo[H_DIM * F_DIM];
// W2/Wc pre-split, transposed [N x K]
__device__ __nv_bfloat16 gW2_hi[H_DIM * H_DIM], gW2_lo[H_DIM * H_DIM];
__device__ __nv_bfloat16 gWc_hi[CPAD  * H_DIM], gWc_lo[CPAD  * H_DIM];

// ---------------------------------------------------------------------------
// CSR build + degree kernels
// ---------------------------------------------------------------------------
__global__ void zero_cnt_kernel() {
    int i = blockIdx.x * blockDim.x + threadIdx.x;
    if (i < NPAD) { g_cntin[i] = 0; g_cntout[i] = 0; g_cnt2[i] = 0; }
}

__global__ void count_kernel(const int* __restrict__ src, const int* __restrict__ dst, int E) {
    int i = blockIdx.x * blockDim.x + threadIdx.x;
    if (i < E) {
        atomicAdd(&g_cntout[src[i]], 1);
        atomicAdd(&g_cntin[dst[i]], 1);
    }
}

__global__ void rsqrt_kernel() {
    int i = blockIdx.x * blockDim.x + threadIdx.x;
    if (i < NPAD) {
        g_degout[i] = rsqrtf((float)max(g_cntout[i], 1));
        g_degin[i]  = rsqrtf((float)max(g_cntin[i], 1));
    }
}

// ---- 3-phase multi-block exclusive scan of g_cntin -> g_rowstart ----------
__global__ void scan_phaseA() {
    int t = threadIdx.x;
    int idx = blockIdx.x * 256 + t;
    int v = (idx < NPAD) ? g_cntin[idx] : 0;
    #pragma unroll
    for (int o = 16; o; o >>= 1) v += __shfl_down_sync(0xffffffffu, v, o);
    __shared__ int ws[8];
    if ((t & 31) == 0) ws[t >> 5] = v;
    __syncthreads();
    if (t < 8) {
        int s = ws[t];
        #pragma unroll
        for (int o = 4; o; o >>= 1) s += __shfl_down_sync(0xffu, s, o);
        if (t == 0) g_blocksum[blockIdx.x] = s;
    }
}

__global__ void scan_phaseB() {
    int t = threadIdx.x;
    int lane = t & 31, w = t >> 5;
    int v = (t < SCAN_B) ? g_blocksum[t] : 0;
    int x = v;
    #pragma unroll
    for (int o = 1; o < 32; o <<= 1) {
        int y = __shfl_up_sync(0xffffffffu, x, o);
        if (lane >= o) x += y;
    }
    __shared__ int ws[8];
    if (lane == 31) ws[w] = x;
    __syncthreads();
    if (t == 0) {
        int s = 0;
        #pragma unroll
        for (int i = 0; i < 8; i++) { int tmp = ws[i]; ws[i] = s; s += tmp; }
    }
    __syncthreads();
    int incl = x + ws[w];
    if (t < SCAN_B) {
        g_blockoff[t] = incl - v;
        if (t == SCAN_B - 1) g_rowstart[NPAD] = incl;
    }
}

__global__ void scan_phaseC() {
    int t = threadIdx.x;
    int idx = blockIdx.x * 256 + t;
    int lane = t & 31, w = t >> 5;
    int v = (idx < NPAD) ? g_cntin[idx] : 0;
    int x = v;
    #pragma unroll
    for (int o = 1; o < 32; o <<= 1) {
        int y = __shfl_up_sync(0xffffffffu, x, o);
        if (lane >= o) x += y;
    }
    __shared__ int ws[8];
    if (lane == 31) ws[w] = x;
    __syncthreads();
    if (t == 0) {
        int s = 0;
        #pragma unroll
        for (int i = 0; i < 8; i++) { int tmp = ws[i]; ws[i] = s; s += tmp; }
    }
    __syncthreads();
    int excl = x - v + ws[w] + g_blockoff[blockIdx.x];
    if (idx < NPAD) g_rowstart[idx] = excl;
}

__global__ void scatter_kernel(const int* __restrict__ src, const int* __restrict__ dst, int E) {
    int i = blockIdx.x * blockDim.x + threadIdx.x;
    if (i < E) {
        int d = dst[i];
        int pos = g_rowstart[d] + atomicAdd(&g_cnt2[d], 1);
        g_srcsorted[pos] = src[i];
    }
}

// ---------------------------------------------------------------------------
// CSR aggregate + finalize: one warp per dst node, fp16 messages.
// If srcscale != null, each gathered row is scaled by srcscale[src]
// (used for layer 1 where H is unscaled).
// X[d] = relu( (sum H[src]*ss) * rsqrt(deg_in[d]) + bias )
// ---------------------------------------------------------------------------
__global__ void csr_agg_kernel(const float* __restrict__ bias,
                               const float* __restrict__ srcscale) {
    int warp = (blockIdx.x * blockDim.x + threadIdx.x) >> 5;
    int lane = threadIdx.x & 31;
    if (warp >= NPAD) return;
    int beg = g_rowstart[warp];
    int end = g_rowstart[warp + 1];
    float4 acc = make_float4(0.f, 0.f, 0.f, 0.f);
    const uint2* Hv = reinterpret_cast<const uint2*>(g_Hh);

    auto addrow = [&](int s) {
        uint2 u = Hv[s * 32 + lane];
        __half2 p0 = *reinterpret_cast<__half2*>(&u.x);
        __half2 p1 = *reinterpret_cast<__half2*>(&u.y);
        float2 f0 = __half22float2(p0);
        float2 f1 = __half22float2(p1);
        float ss = srcscale ? __ldg(&srcscale[s]) : 1.f;
        acc.x = fmaf(f0.x, ss, acc.x);
        acc.y = fmaf(f0.y, ss, acc.y);
        acc.z = fmaf(f1.x, ss, acc.z);
        acc.w = fmaf(f1.y, ss, acc.w);
    };

    int e = beg;
    for (; e + 7 < end; e += 8) {
        int s0 = g_srcsorted[e],   s1 = g_srcsorted[e+1], s2 = g_srcsorted[e+2], s3 = g_srcsorted[e+3];
        int s4 = g_srcsorted[e+4], s5 = g_srcsorted[e+5], s6 = g_srcsorted[e+6], s7 = g_srcsorted[e+7];
        addrow(s0); addrow(s1); addrow(s2); addrow(s3);
        addrow(s4); addrow(s5); addrow(s6); addrow(s7);
    }
    for (; e < end; e++) addrow(g_srcsorted[e]);

    float rs = g_degin[warp];
    float4 b = reinterpret_cast<const float4*>(bias)[lane];
    float4 x;
    x.x = fmaxf(acc.x * rs + b.x, 0.f);
    x.y = fmaxf(acc.y * rs + b.y, 0.f);
    x.z = fmaxf(acc.z * rs + b.z, 0.f);
    x.w = fmaxf(acc.w * rs + b.w, 0.f);
    reinterpret_cast<float4*>(g_X)[warp * 32 + lane] = x;
}

// ---------------------------------------------------------------------------
// fused weight: Wfused = Wp @ W1 (256x128), output transposed+split bf16;
// also bfused = bp @ W1.
// thread i<32768: k = i>>7, n = i&127 (Wp row broadcast, W1 col coalesced)
// ---------------------------------------------------------------------------
__global__ void fuse_W_kernel(const float* __restrict__ Wp,
                              const float* __restrict__ W1,
                              const float* __restrict__ bp) {
    int i = blockIdx.x * blockDim.x + threadIdx.x;
    if (i < H_DIM * F_DIM) {
        int k = i >> 7;          // 0..255
        int n = i & 127;         // 0..127
        float s = 0.f;
        #pragma unroll 8
        for (int j = 0; j < H_DIM; j++)
            s = fmaf(Wp[k * H_DIM + j], W1[j * H_DIM + n], s);
        int idx = n * F_DIM + k;           // [n][k] transposed layout
        __nv_bfloat16 h = __float2bfloat16_rn(s);
        gWf_hi[idx] = h;
        gWf_lo[idx] = __float2bfloat16_rn(s - __bfloat162float(h));
    } else if (i < H_DIM * F_DIM + H_DIM) {
        int n = i - H_DIM * F_DIM;
        float s = 0.f;
        for (int j = 0; j < H_DIM; j++)
            s = fmaf(bp[j], W1[j * H_DIM + n], s);
        g_bfused[n] = s;
    }
}

// ---------------------------------------------------------------------------
// weight pre-split: W[K x N] -> bf16 hi/lo [Npad x K] (transposed, padded)
// ---------------------------------------------------------------------------
__device__ __forceinline__ void wsplit_one(const float* W, __nv_bfloat16* hi, __nv_bfloat16* lo,
                                           int K, int N, int Npad, int i) {
    int n = i / K, k = i - n * K;
    float v = (n < N) ? W[(size_t)k * N + n] : 0.f;
    __nv_bfloat16 h = __float2bfloat16_rn(v);
    float r = v - __bfloat162float(h);
    hi[i] = h;
    lo[i] = __float2bfloat16_rn(r);
}

// merged presplit for W2 (16384) and Wc (8192) in one launch
__global__ void presplit_W2c_kernel(const float* __restrict__ W2,
                                    const float* __restrict__ Wc) {
    int i = blockIdx.x * blockDim.x + threadIdx.x;
    if (i < 16384) {
        wsplit_one(W2, gW2_hi, gW2_lo, H_DIM, H_DIM, H_DIM, i);
    } else if (i < 24576) {
        wsplit_one(Wc, gWc_hi, gWc_lo, H_DIM, C_DIM, CPAD, i - 16384);
    }
}

// ---------------------------------------------------------------------------
// split-BF16 GEMM (3 products: hh + lh + hl): C[M,N] = A[M,K] @ Wt[N x K]
// BM=128, BN=64, BK=32, 256 threads (8 warps: 4m x 2n), warp tile 32x32.
// A: LDG fp32 -> split to bf16 hi/lo in regs -> STS -> ldmatrix.b16
// B: cp.async pre-split bf16 tiles -> ldmatrix.b16
// mma.sync.m16n8k16.bf16, fp32 accum.
// ---------------------------------------------------------------------------
#define OFF_AH   0
#define OFF_AL   10240                    // 128 * 80
#define OFF_BH   20480
#define OFF_BL   25600                    // + 64 * 80
#define STG_BYTES 30720
#define SMEM_TOT (2 * STG_BYTES)          // 61440

__device__ __forceinline__ void cp16(uint32_t saddr, const void* g) {
    asm volatile("cp.async.ca.shared.global [%0], [%1], 16;" :: "r"(saddr), "l"(g) : "memory");
}

__device__ __forceinline__ void ldsm4(uint32_t& r0, uint32_t& r1, uint32_t& r2, uint32_t& r3,
                                      uint32_t saddr) {
    asm volatile("ldmatrix.sync.aligned.m8n8.x4.shared.b16 {%0,%1,%2,%3}, [%4];"
                 : "=r"(r0), "=r"(r1), "=r"(r2), "=r"(r3) : "r"(saddr));
}

__device__ __forceinline__ void mma_bf16(
    float& d0, float& d1, float& d2, float& d3,
    uint32_t a0, uint32_t a1, uint32_t a2, uint32_t a3,
    uint32_t b0, uint32_t b1)
{
    asm volatile(
        "mma.sync.aligned.m16n8k16.row.col.f32.bf16.bf16.f32 "
        "{%0,%1,%2,%3}, {%4,%5,%6,%7}, {%8,%9}, {%0,%1,%2,%3};"
        : "+f"(d0), "+f"(d1), "+f"(d2), "+f"(d3)
        : "r"(a0), "r"(a1), "r"(a2), "r"(a3), "r"(b0), "r"(b1));
}

// pack two floats' bf16 hi parts / lo parts
__device__ __forceinline__ void split_pack2(float x, float y, uint32_t& hi2, uint32_t& lo2) {
    __nv_bfloat162 h = __floats2bfloat162_rn(x, y);
    float rx = x - __bfloat162float(__low2bfloat16(h));
    float ry = y - __bfloat162float(__high2bfloat16(h));
    __nv_bfloat162 l = __floats2bfloat162_rn(rx, ry);
    hi2 = *reinterpret_cast<uint32_t*>(&h);
    lo2 = *reinterpret_cast<uint32_t*>(&l);
}

__global__ __launch_bounds__(256) void mma_gemm_kernel(
    const float* __restrict__ A, int Mvalid,
    const __nv_bfloat16* __restrict__ Bhi, const __nv_bfloat16* __restrict__ Blo, int K,
    float* __restrict__ C, __half* __restrict__ Chalf, int ldC, int Mout, int Nout,
    const float* __restrict__ bias, const float* __restrict__ rowscale)
{
    extern __shared__ uint8_t smem_raw[];
    const uint32_t smem_b = (uint32_t)__cvta_generic_to_shared(smem_raw);

    const int tid  = threadIdx.x;
    const int lane = tid & 31;
    const int warp = tid >> 5;
    const int wm   = warp >> 1;          // 0..3
    const int wn   = warp & 1;           // 0..1
    const int rowBase = blockIdx.y * 128;
    const int colBase = blockIdx.x * 64;
    const int nStages = K >> 5;

    float acc[2][4][4];
    #pragma unroll
    for (int i = 0; i < 2; i++)
        #pragma unroll
        for (int j = 0; j < 4; j++)
            #pragma unroll
            for (int l = 0; l < 4; l++) acc[i][j][l] = 0.f;

    // A loader slots: 4 float4/thread; row = idx>>3, c4 = idx&7 (32 floats/row)
    int aRow[4], aC4[4];
    #pragma unroll
    for (int i = 0; i < 4; i++) {
        int idx = tid + i * 256;
        aRow[i] = idx >> 3;
        aC4[i]  = idx & 7;
    }
    // B loader slot: 1 per thread: n = tid>>2, c16 = tid&3
    const int bN = tid >> 2, bC = tid & 3;

    float4 pa[4];
    auto loadA = [&](int s) {
        const int k0 = s * 32;
        #pragma unroll
        for (int i = 0; i < 4; i++) {
            int gr = rowBase + aRow[i];
            pa[i] = (gr < Mvalid)
                  ? *reinterpret_cast<const float4*>(A + (size_t)gr * K + k0 + aC4[i] * 4)
                  : make_float4(0.f, 0.f, 0.f, 0.f);
        }
    };
    auto storeA = [&](int b) {
        #pragma unroll
        for (int i = 0; i < 4; i++) {
            uint32_t h01, l01, h23, l23;
            split_pack2(pa[i].x, pa[i].y, h01, l01);
            split_pack2(pa[i].z, pa[i].w, h23, l23);
            uint32_t off = aRow[i] * 80 + aC4[i] * 8;
            *reinterpret_cast<uint2*>(smem_raw + off + b * STG_BYTES + OFF_AH) = make_uint2(h01, h23);
            *reinterpret_cast<uint2*>(smem_raw + off + b * STG_BYTES + OFF_AL) = make_uint2(l01, l23);
        }
    };
    auto issueB = [&](int s, int b) {
        const int k0 = s * 32;
        const uint32_t sb = smem_b + b * STG_BYTES;
        size_t g = (size_t)(colBase + bN) * K + k0 + bC * 8;
        uint32_t off = bN * 80 + bC * 16;
        cp16(sb + OFF_BH + off, Bhi + g);
        cp16(sb + OFF_BL + off, Blo + g);
        asm volatile("cp.async.commit_group;" ::: "memory");
    };

    loadA(0);
    issueB(0, 0);

    for (int s = 0; s < nStages; s++) {
        const int b = s & 1;
        storeA(b);
        if (s + 1 < nStages) {
            loadA(s + 1);
            issueB(s + 1, b ^ 1);
            asm volatile("cp.async.wait_group 1;" ::: "memory");
        } else {
            asm volatile("cp.async.wait_group 0;" ::: "memory");
        }
        __syncthreads();

        const uint32_t sAh = smem_b + b * STG_BYTES + OFF_AH;
        const uint32_t sAl = smem_b + b * STG_BYTES + OFF_AL;
        const uint32_t sBh = smem_b + b * STG_BYTES + OFF_BH;
        const uint32_t sBl = smem_b + b * STG_BYTES + OFF_BL;

        // ldmatrix lane address components
        const int aLRow = lane & 15;               // row within 16-row tile
        const int aKoff = (lane >> 4) * 8;         // +8 k for mats 2,3
        const int bLN   = ((lane >> 4) << 3) + (lane & 7);  // n within 16-col pair
        const int bKoff = ((lane >> 3) & 1) * 8;   // +8 k for mats 1,3

        #pragma unroll
        for (int kk = 0; kk < 2; kk++) {
            const int kb = kk * 16;
            uint32_t ah[2][4], al[2][4];
            #pragma unroll
            for (int mt = 0; mt < 2; mt++) {
                int r = (wm * 2 + mt) * 16 + aLRow;
                uint32_t ad = sAh + r * 80 + (kb + aKoff) * 2;
                ldsm4(ah[mt][0], ah[mt][1], ah[mt][2], ah[mt][3], ad);
                ad = sAl + r * 80 + (kb + aKoff) * 2;
                ldsm4(al[mt][0], al[mt][1], al[mt][2], al[mt][3], ad);
            }
            uint32_t bh[2][4], bl[2][4];
            #pragma unroll
            for (int p = 0; p < 2; p++) {
                int n = wn * 32 + p * 16 + bLN;
                uint32_t bd = sBh + n * 80 + (kb + bKoff) * 2;
                ldsm4(bh[p][0], bh[p][1], bh[p][2], bh[p][3], bd);
                bd = sBl + n * 80 + (kb + bKoff) * 2;
                ldsm4(bl[p][0], bl[p][1], bl[p][2], bl[p][3], bd);
            }
            #pragma unroll
            for (int mt = 0; mt < 2; mt++) {
                #pragma unroll
                for (int nt = 0; nt < 4; nt++) {
                    float* d = acc[mt][nt];
                    int p = nt >> 1, q = (nt & 1) * 2;
                    uint32_t b0h = bh[p][q], b1h = bh[p][q + 1];
                    uint32_t b0l = bl[p][q], b1l = bl[p][q + 1];
                    mma_bf16(d[0], d[1], d[2], d[3],
                             ah[mt][0], ah[mt][1], ah[mt][2], ah[mt][3], b0h, b1h);
                    mma_bf16(d[0], d[1], d[2], d[3],
                             al[mt][0], al[mt][1], al[mt][2], al[mt][3], b0h, b1h);
                    mma_bf16(d[0], d[1], d[2], d[3],
                             ah[mt][0], ah[mt][1], ah[mt][2], ah[mt][3], b0l, b1l);
                }
            }
        }
        __syncthreads();
    }

    // epilogue
    #pragma unroll
    for (int mt = 0; mt < 2; mt++) {
        int r0 = rowBase + wm * 32 + mt * 16 + (lane >> 2);
        int r1 = r0 + 8;
        float rs0 = rowscale ? rowscale[r0] : 1.f;
        float rs1 = rowscale ? rowscale[r1] : 1.f;
        #pragma unroll
        for (int nt = 0; nt < 4; nt++) {
            int c0 = colBase + wn * 32 + nt * 8 + (lane & 3) * 2;
            float b0 = (bias && c0 < Nout)     ? bias[c0]     : 0.f;
            float b1 = (bias && c0 + 1 < Nout) ? bias[c0 + 1] : 0.f;
            float v00 = acc[mt][nt][0] * rs0 + b0;
            float v01 = acc[mt][nt][1] * rs0 + b1;
            float v10 = acc[mt][nt][2] * rs1 + b0;
            float v11 = acc[mt][nt][3] * rs1 + b1;
            if (Chalf) {
                *reinterpret_cast<__half2*>(Chalf + (size_t)r0 * ldC + c0) = __floats2half2_rn(v00, v01);
                *reinterpret_cast<__half2*>(Chalf + (size_t)r1 * ldC + c0) = __floats2half2_rn(v10, v11);
            } else if (c0 + 1 < Nout) {
                if (r0 < Mout) *reinterpret_cast<float2*>(C + (size_t)r0 * ldC + c0) = make_float2(v00, v01);
                if (r1 < Mout) *reinterpret_cast<float2*>(C + (size_t)r1 * ldC + c0) = make_float2(v10, v11);
            } else if (c0 < Nout) {
                if (r0 < Mout) C[(size_t)r0 * ldC + c0] = v00;
                if (r1 < Mout) C[(size_t)r1 * ldC + c0] = v10;
            }
        }
    }
}

// ---------------------------------------------------------------------------
extern "C" void kernel_launch(void* const* d_in, const int* in_sizes, int n_in,
                              void* d_out, int out_size)
{
    const float* n_feats = (const float*)d_in[0];
    const int*   src     = (const int*)  d_in[1];
    const int*   dst     = (const int*)  d_in[2];
    const float* Wp      = (const float*)d_in[3];
    const float* bp      = (const float*)d_in[4];
    const float* W1      = (const float*)d_in[5];
    const float* b1      = (const float*)d_in[6];
    const float* W2      = (const float*)d_in[7];
    const float* b2      = (const float*)d_in[8];
    const float* Wc      = (const float*)d_in[9];
    const float* bc      = (const float*)d_in[10];
    float* out = (float*)d_out;
    int E = in_sizes[1];

    float *X, *degout, *bfused;
    __half *Hh;
    __nv_bfloat16 *Wfhi, *Wflo, *W2hi, *W2lo, *Wchi, *Wclo;
    cudaGetSymbolAddress((void**)&X, g_X);
    cudaGetSymbolAddress((void**)&Hh, g_Hh);
    cudaGetSymbolAddress((void**)&degout, g_degout);
    cudaGetSymbolAddress((void**)&bfused, g_bfused);
    cudaGetSymbolAddress((void**)&Wfhi, gWf_hi); cudaGetSymbolAddress((void**)&Wflo, gWf_lo);
    cudaGetSymbolAddress((void**)&W2hi, gW2_hi); cudaGetSymbolAddress((void**)&W2lo, gW2_lo);
    cudaGetSymbolAddress((void**)&Wchi, gWc_hi); cudaGetSymbolAddress((void**)&Wclo, gWc_lo);

    // one-time host-side setup (no device allocation)
    static bool init_done = false;
    static cudaStream_t s2 = nullptr;
    static cudaEvent_t evFork, evCsr;
    if (!init_done) {
        cudaFuncSetAttribute(mma_gemm_kernel, cudaFuncAttributeMaxDynamicSharedMemorySize,
                             SMEM_TOT);
        cudaStreamCreateWithFlags(&s2, cudaStreamNonBlocking);
        cudaEventCreateWithFlags(&evFork, cudaEventDisableTiming);
        cudaEventCreateWithFlags(&evCsr,  cudaEventDisableTiming);
        init_done = true;
    }

    const int T = 256;
    int nodeBlocks = (NPAD + T - 1) / T;
    int edgeBlocks = (E + T - 1) / T;
    int aggBlocks  = (NPAD + 7) / 8;

    dim3 gH(2, NPAD / 128);
    dim3 gC(1, NPAD / 128);

    // ---- fork: CSR build + degree + W2/Wc presplit on s2 ----
    cudaEventRecord(evFork, 0);
    cudaStreamWaitEvent(s2, evFork, 0);

    presplit_W2c_kernel<<<(24576 + T - 1) / T, T, 0, s2>>>(W2, Wc);
    zero_cnt_kernel<<<nodeBlocks, T, 0, s2>>>();
    count_kernel<<<edgeBlocks, T, 0, s2>>>(src, dst, E);
    rsqrt_kernel<<<nodeBlocks, T, 0, s2>>>();
    scan_phaseA<<<SCAN_B, T, 0, s2>>>();
    scan_phaseB<<<1, T, 0, s2>>>();
    scan_phaseC<<<SCAN_B, T, 0, s2>>>();
    scatter_kernel<<<edgeBlocks, T, 0, s2>>>(src, dst, E);
    cudaEventRecord(evCsr, s2);   // everything on s2 done (weights, degrees, CSR)

    // stream 0: fused weight (Wp@W1 + bp@W1), then the fused GEMM
    // H = n_feats @ Wfused + bfused  (fp16 out, UNSCALED — scale applied in agg1)
    fuse_W_kernel<<<(H_DIM * F_DIM + H_DIM + T - 1) / T, T>>>(Wp, W1, bp);
    mma_gemm_kernel<<<gH, T, SMEM_TOT>>>(n_feats, N_NODES, Wfhi, Wflo, F_DIM,
                                         nullptr, Hh, H_DIM, NPAD, H_DIM, bfused, nullptr);

    // ---- GCN layer 1 aggregation (needs CSR + degrees; srcscale=degout) ----
    cudaStreamWaitEvent(0, evCsr, 0);
    csr_agg_kernel<<<aggBlocks, T>>>(b1, degout);

    // ---- GCN layer 2: H = X @ W2 row-scaled; agg without srcscale ----
    mma_gemm_kernel<<<gH, T, SMEM_TOT>>>(X, NPAD, W2hi, W2lo, H_DIM,
                                         nullptr, Hh, H_DIM, NPAD, H_DIM, nullptr, degout);
    csr_agg_kernel<<<aggBlocks, T>>>(b2, nullptr);

    // classifier: out = X @ Wc + bc  (fp32 out)
    mma_gemm_kernel<<<gC, T, SMEM_TOT>>>(X, NPAD, Wchi, Wclo, H_DIM,
                                         out, nullptr, C_DIM, N_NODES, C_DIM, bc, nullptr);
}

// round 16
// speedup vs baseline: 1.6807x; 1.0368x over previous
#include <cuda_runtime.h>
#include <cuda_bf16.h>
#include <cuda_fp16.h>
#include <cstdint>

#define N_NODES 50000
#define NPAD    50048            // 391 * 128
#define H_DIM   128
#define F_DIM   256
#define C_DIM   40
#define CPAD    64
#define E_CAP   800000
#define SCAN_B  196              // ceil(NPAD / 256)

// ---------------------------------------------------------------------------
// Global scratch (static device globals)
// ---------------------------------------------------------------------------
__device__ __half g_Xh[NPAD * H_DIM];    // activations (fp16)
__device__ __half g_Hh[NPAD * H_DIM];    // messages (fp16)
__device__ float  g_degout[NPAD];        // rsqrt(max(deg_out,1))
__device__ float  g_degin [NPAD];
__device__ int    g_cntin[NPAD], g_cntout[NPAD], g_cnt2[NPAD];
__device__ int    g_rowstart[NPAD + 1];
__device__ int    g_srcsorted[E_CAP];
__device__ int    g_blocksum[SCAN_B];
__device__ int    g_blockoff[SCAN_B];
__device__ float  g_bfused[H_DIM];       // bp @ W1
// fused weight Wp@W1, split bf16, TRANSPOSED [n (128) x k (256)]
__device__ __nv_bfloat16 gWf_hi[H_DIM * F_DIM], gWf_lo[H_DIM * F_DIM];
// W2/Wc pre-split, transposed [N x K]
__device__ __nv_bfloat16 gW2_hi[H_DIM * H_DIM], gW2_lo[H_DIM * H_DIM];
__device__ __nv_bfloat16 gWc_hi[CPAD  * H_DIM], gWc_lo[CPAD  * H_DIM];

// ---------------------------------------------------------------------------
// CSR build + degree kernels
// ---------------------------------------------------------------------------
__global__ void zero_cnt_kernel() {
    int i = blockIdx.x * blockDim.x + threadIdx.x;
    if (i < NPAD) { g_cntin[i] = 0; g_cntout[i] = 0; g_cnt2[i] = 0; }
}

__global__ void count_kernel(const int* __restrict__ src, const int* __restrict__ dst, int E) {
    int i = blockIdx.x * blockDim.x + threadIdx.x;
    if (i < E) {
        atomicAdd(&g_cntout[src[i]], 1);
        atomicAdd(&g_cntin[dst[i]], 1);
    }
}

__global__ void rsqrt_kernel() {
    int i = blockIdx.x * blockDim.x + threadIdx.x;
    if (i < NPAD) {
        g_degout[i] = rsqrtf((float)max(g_cntout[i], 1));
        g_degin[i]  = rsqrtf((float)max(g_cntin[i], 1));
    }
}

// ---- 3-phase multi-block exclusive scan of g_cntin -> g_rowstart ----------
__global__ void scan_phaseA() {
    int t = threadIdx.x;
    int idx = blockIdx.x * 256 + t;
    int v = (idx < NPAD) ? g_cntin[idx] : 0;
    #pragma unroll
    for (int o = 16; o; o >>= 1) v += __shfl_down_sync(0xffffffffu, v, o);
    __shared__ int ws[8];
    if ((t & 31) == 0) ws[t >> 5] = v;
    __syncthreads();
    if (t < 8) {
        int s = ws[t];
        #pragma unroll
        for (int o = 4; o; o >>= 1) s += __shfl_down_sync(0xffu, s, o);
        if (t == 0) g_blocksum[blockIdx.x] = s;
    }
}

__global__ void scan_phaseB() {
    int t = threadIdx.x;
    int lane = t & 31, w = t >> 5;
    int v = (t < SCAN_B) ? g_blocksum[t] : 0;
    int x = v;
    #pragma unroll
    for (int o = 1; o < 32; o <<= 1) {
        int y = __shfl_up_sync(0xffffffffu, x, o);
        if (lane >= o) x += y;
    }
    __shared__ int ws[8];
    if (lane == 31) ws[w] = x;
    __syncthreads();
    if (t == 0) {
        int s = 0;
        #pragma unroll
        for (int i = 0; i < 8; i++) { int tmp = ws[i]; ws[i] = s; s += tmp; }
    }
    __syncthreads();
    int incl = x + ws[w];
    if (t < SCAN_B) {
        g_blockoff[t] = incl - v;
        if (t == SCAN_B - 1) g_rowstart[NPAD] = incl;
    }
}

__global__ void scan_phaseC() {
    int t = threadIdx.x;
    int idx = blockIdx.x * 256 + t;
    int lane = t & 31, w = t >> 5;
    int v = (idx < NPAD) ? g_cntin[idx] : 0;
    int x = v;
    #pragma unroll
    for (int o = 1; o < 32; o <<= 1) {
        int y = __shfl_up_sync(0xffffffffu, x, o);
        if (lane >= o) x += y;
    }
    __shared__ int ws[8];
    if (lane == 31) ws[w] = x;
    __syncthreads();
    if (t == 0) {
        int s = 0;
        #pragma unroll
        for (int i = 0; i < 8; i++) { int tmp = ws[i]; ws[i] = s; s += tmp; }
    }
    __syncthreads();
    int excl = x - v + ws[w] + g_blockoff[blockIdx.x];
    if (idx < NPAD) g_rowstart[idx] = excl;
}

__global__ void scatter_kernel(const int* __restrict__ src, const int* __restrict__ dst, int E) {
    int i = blockIdx.x * blockDim.x + threadIdx.x;
    if (i < E) {
        int d = dst[i];
        int pos = g_rowstart[d] + atomicAdd(&g_cnt2[d], 1);
        g_srcsorted[pos] = src[i];
    }
}

// ---------------------------------------------------------------------------
// CSR aggregate + finalize: one warp per dst node, fp16 messages, fp16 X out.
// X[d] = relu( (sum H[src]*ss) * rsqrt(deg_in[d]) + bias )
// ---------------------------------------------------------------------------
__global__ void csr_agg_kernel(const float* __restrict__ bias,
                               const float* __restrict__ srcscale) {
    int warp = (blockIdx.x * blockDim.x + threadIdx.x) >> 5;
    int lane = threadIdx.x & 31;
    if (warp >= NPAD) return;
    int beg = g_rowstart[warp];
    int end = g_rowstart[warp + 1];
    float4 acc = make_float4(0.f, 0.f, 0.f, 0.f);
    const uint2* Hv = reinterpret_cast<const uint2*>(g_Hh);

    auto addrow = [&](int s) {
        uint2 u = Hv[s * 32 + lane];
        __half2 p0 = *reinterpret_cast<__half2*>(&u.x);
        __half2 p1 = *reinterpret_cast<__half2*>(&u.y);
        float2 f0 = __half22float2(p0);
        float2 f1 = __half22float2(p1);
        float ss = srcscale ? __ldg(&srcscale[s]) : 1.f;
        acc.x = fmaf(f0.x, ss, acc.x);
        acc.y = fmaf(f0.y, ss, acc.y);
        acc.z = fmaf(f1.x, ss, acc.z);
        acc.w = fmaf(f1.y, ss, acc.w);
    };

    int e = beg;
    for (; e + 7 < end; e += 8) {
        int s0 = g_srcsorted[e],   s1 = g_srcsorted[e+1], s2 = g_srcsorted[e+2], s3 = g_srcsorted[e+3];
        int s4 = g_srcsorted[e+4], s5 = g_srcsorted[e+5], s6 = g_srcsorted[e+6], s7 = g_srcsorted[e+7];
        addrow(s0); addrow(s1); addrow(s2); addrow(s3);
        addrow(s4); addrow(s5); addrow(s6); addrow(s7);
    }
    for (; e < end; e++) addrow(g_srcsorted[e]);

    float rs = g_degin[warp];
    float4 b = reinterpret_cast<const float4*>(bias)[lane];
    __half2 o0 = __floats2half2_rn(fmaxf(acc.x * rs + b.x, 0.f),
                                   fmaxf(acc.y * rs + b.y, 0.f));
    __half2 o1 = __floats2half2_rn(fmaxf(acc.z * rs + b.z, 0.f),
                                   fmaxf(acc.w * rs + b.w, 0.f));
    uint2 o;
    o.x = *reinterpret_cast<uint32_t*>(&o0);
    o.y = *reinterpret_cast<uint32_t*>(&o1);
    reinterpret_cast<uint2*>(g_Xh)[warp * 32 + lane] = o;
}

// ---------------------------------------------------------------------------
// fused weight: Wfused = Wp @ W1 (256x128), transposed+split bf16; bfused = bp@W1
// ---------------------------------------------------------------------------
__global__ void fuse_W_kernel(const float* __restrict__ Wp,
                              const float* __restrict__ W1,
                              const float* __restrict__ bp) {
    int i = blockIdx.x * blockDim.x + threadIdx.x;
    if (i < H_DIM * F_DIM) {
        int k = i >> 7;          // 0..255
        int n = i & 127;         // 0..127
        float s = 0.f;
        #pragma unroll 8
        for (int j = 0; j < H_DIM; j++)
            s = fmaf(Wp[k * H_DIM + j], W1[j * H_DIM + n], s);
        int idx = n * F_DIM + k;           // [n][k] transposed layout
        __nv_bfloat16 h = __float2bfloat16_rn(s);
        gWf_hi[idx] = h;
        gWf_lo[idx] = __float2bfloat16_rn(s - __bfloat162float(h));
    } else if (i < H_DIM * F_DIM + H_DIM) {
        int n = i - H_DIM * F_DIM;
        float s = 0.f;
        for (int j = 0; j < H_DIM; j++)
            s = fmaf(bp[j], W1[j * H_DIM + n], s);
        g_bfused[n] = s;
    }
}

// ---------------------------------------------------------------------------
// weight pre-split: W[K x N] -> bf16 hi/lo [Npad x K] (transposed, padded)
// ---------------------------------------------------------------------------
__device__ __forceinline__ void wsplit_one(const float* W, __nv_bfloat16* hi, __nv_bfloat16* lo,
                                           int K, int N, int Npad, int i) {
    int n = i / K, k = i - n * K;
    float v = (n < N) ? W[(size_t)k * N + n] : 0.f;
    __nv_bfloat16 h = __float2bfloat16_rn(v);
    float r = v - __bfloat162float(h);
    hi[i] = h;
    lo[i] = __float2bfloat16_rn(r);
}

// merged presplit for W2 (16384) and Wc (8192) in one launch
__global__ void presplit_W2c_kernel(const float* __restrict__ W2,
                                    const float* __restrict__ Wc) {
    int i = blockIdx.x * blockDim.x + threadIdx.x;
    if (i < 16384) {
        wsplit_one(W2, gW2_hi, gW2_lo, H_DIM, H_DIM, H_DIM, i);
    } else if (i < 24576) {
        wsplit_one(Wc, gWc_hi, gWc_lo, H_DIM, C_DIM, CPAD, i - 16384);
    }
}

// ---------------------------------------------------------------------------
// split-BF16 GEMM (3 products: hh + lh + hl): C[M,N] = A[M,K] @ Wt[N x K]
// BM=128, BN=64, BK=32, 256 threads (8 warps: 4m x 2n), warp tile 32x32.
// A path: fp32 (AHALF=false) or fp16 (AHALF=true; exact bf16 hi+lo repr).
// ---------------------------------------------------------------------------
#define OFF_AH   0
#define OFF_AL   10240                    // 128 * 80
#define OFF_BH   20480
#define OFF_BL   25600                    // + 64 * 80
#define STG_BYTES 30720
#define SMEM_TOT (2 * STG_BYTES)          // 61440

__device__ __forceinline__ void cp16(uint32_t saddr, const void* g) {
    asm volatile("cp.async.ca.shared.global [%0], [%1], 16;" :: "r"(saddr), "l"(g) : "memory");
}

__device__ __forceinline__ void ldsm4(uint32_t& r0, uint32_t& r1, uint32_t& r2, uint32_t& r3,
                                      uint32_t saddr) {
    asm volatile("ldmatrix.sync.aligned.m8n8.x4.shared.b16 {%0,%1,%2,%3}, [%4];"
                 : "=r"(r0), "=r"(r1), "=r"(r2), "=r"(r3) : "r"(saddr));
}

__device__ __forceinline__ void mma_bf16(
    float& d0, float& d1, float& d2, float& d3,
    uint32_t a0, uint32_t a1, uint32_t a2, uint32_t a3,
    uint32_t b0, uint32_t b1)
{
    asm volatile(
        "mma.sync.aligned.m16n8k16.row.col.f32.bf16.bf16.f32 "
        "{%0,%1,%2,%3}, {%4,%5,%6,%7}, {%8,%9}, {%0,%1,%2,%3};"
        : "+f"(d0), "+f"(d1), "+f"(d2), "+f"(d3)
        : "r"(a0), "r"(a1), "r"(a2), "r"(a3), "r"(b0), "r"(b1));
}

// pack two floats' bf16 hi parts / lo parts
__device__ __forceinline__ void split_pack2(float x, float y, uint32_t& hi2, uint32_t& lo2) {
    __nv_bfloat162 h = __floats2bfloat162_rn(x, y);
    float rx = x - __bfloat162float(__low2bfloat16(h));
    float ry = y - __bfloat162float(__high2bfloat16(h));
    __nv_bfloat162 l = __floats2bfloat162_rn(rx, ry);
    hi2 = *reinterpret_cast<uint32_t*>(&h);
    lo2 = *reinterpret_cast<uint32_t*>(&l);
}

template<bool AHALF>
__global__ __launch_bounds__(256) void mma_gemm_kernel(
    const void* __restrict__ Araw, int Mvalid,
    const __nv_bfloat16* __restrict__ Bhi, const __nv_bfloat16* __restrict__ Blo, int K,
    float* __restrict__ C, __half* __restrict__ Chalf, int ldC, int Mout, int Nout,
    const float* __restrict__ bias, const float* __restrict__ rowscale)
{
    extern __shared__ uint8_t smem_raw[];
    const uint32_t smem_b = (uint32_t)__cvta_generic_to_shared(smem_raw);

    const int tid  = threadIdx.x;
    const int lane = tid & 31;
    const int warp = tid >> 5;
    const int wm   = warp >> 1;          // 0..3
    const int wn   = warp & 1;           // 0..1
    const int rowBase = blockIdx.y * 128;
    const int colBase = blockIdx.x * 64;
    const int nStages = K >> 5;

    float acc[2][4][4];
    #pragma unroll
    for (int i = 0; i < 2; i++)
        #pragma unroll
        for (int j = 0; j < 4; j++)
            #pragma unroll
            for (int l = 0; l < 4; l++) acc[i][j][l] = 0.f;

    // fp32-A slots: 4 float4/thread (row = idx>>3, c4 = idx&7, 32 floats/row)
    // fp16-A slots: 2 uint4/thread  (row = idx>>2, c16 = idx&3, 4x16B per row)
    int aRow[4], aC4[4];
    #pragma unroll
    for (int i = 0; i < 4; i++) {
        int idx = tid + i * 256;
        if (AHALF) { aRow[i] = idx >> 2; aC4[i] = idx & 3; }
        else       { aRow[i] = idx >> 3; aC4[i] = idx & 7; }
    }
    // B loader slot: n = tid>>2, c16 = tid&3
    const int bN = tid >> 2, bC = tid & 3;

    float4 pa[4];
    uint4  ph[2];
    auto loadA = [&](int s) {
        const int k0 = s * 32;
        if (AHALF) {
            const __half* A = (const __half*)Araw;
            #pragma unroll
            for (int i = 0; i < 2; i++) {
                int gr = rowBase + aRow[i];
                ph[i] = (gr < Mvalid)
                      ? *reinterpret_cast<const uint4*>(A + (size_t)gr * K + k0 + aC4[i] * 8)
                      : make_uint4(0u, 0u, 0u, 0u);
            }
        } else {
            const float* A = (const float*)Araw;
            #pragma unroll
            for (int i = 0; i < 4; i++) {
                int gr = rowBase + aRow[i];
                pa[i] = (gr < Mvalid)
                      ? *reinterpret_cast<const float4*>(A + (size_t)gr * K + k0 + aC4[i] * 4)
                      : make_float4(0.f, 0.f, 0.f, 0.f);
            }
        }
    };
    auto storeA = [&](int b) {
        if (AHALF) {
            #pragma unroll
            for (int i = 0; i < 2; i++) {
                uint32_t hw[4], lw[4];
                #pragma unroll
                for (int j = 0; j < 4; j++) {
                    uint32_t bits = (&ph[i].x)[j];
                    float2 f = __half22float2(*reinterpret_cast<__half2*>(&bits));
                    split_pack2(f.x, f.y, hw[j], lw[j]);
                }
                uint32_t off = aRow[i] * 80 + aC4[i] * 16;
                *reinterpret_cast<uint4*>(smem_raw + off + b * STG_BYTES + OFF_AH) =
                    make_uint4(hw[0], hw[1], hw[2], hw[3]);
                *reinterpret_cast<uint4*>(smem_raw + off + b * STG_BYTES + OFF_AL) =
                    make_uint4(lw[0], lw[1], lw[2], lw[3]);
            }
        } else {
            #pragma unroll
            for (int i = 0; i < 4; i++) {
                uint32_t h01, l01, h23, l23;
                split_pack2(pa[i].x, pa[i].y, h01, l01);
                split_pack2(pa[i].z, pa[i].w, h23, l23);
                uint32_t off = aRow[i] * 80 + aC4[i] * 8;
                *reinterpret_cast<uint2*>(smem_raw + off + b * STG_BYTES + OFF_AH) = make_uint2(h01, h23);
                *reinterpret_cast<uint2*>(smem_raw + off + b * STG_BYTES + OFF_AL) = make_uint2(l01, l23);
            }
        }
    };
    auto issueB = [&](int s, int b) {
        const int k0 = s * 32;
        const uint32_t sb = smem_b + b * STG_BYTES;
        size_t g = (size_t)(colBase + bN) * K + k0 + bC * 8;
        uint32_t off = bN * 80 + bC * 16;
        cp16(sb + OFF_BH + off, Bhi + g);
        cp16(sb + OFF_BL + off, Blo + g);
        asm volatile("cp.async.commit_group;" ::: "memory");
    };

    loadA(0);
    issueB(0, 0);

    for (int s = 0; s < nStages; s++) {
        const int b = s & 1;
        storeA(b);
        if (s + 1 < nStages) {
            loadA(s + 1);
            issueB(s + 1, b ^ 1);
            asm volatile("cp.async.wait_group 1;" ::: "memory");
        } else {
            asm volatile("cp.async.wait_group 0;" ::: "memory");
        }
        __syncthreads();

        const uint32_t sAh = smem_b + b * STG_BYTES + OFF_AH;
        const uint32_t sAl = smem_b + b * STG_BYTES + OFF_AL;
        const uint32_t sBh = smem_b + b * STG_BYTES + OFF_BH;
        const uint32_t sBl = smem_b + b * STG_BYTES + OFF_BL;

        const int aLRow = lane & 15;
        const int aKoff = (lane >> 4) * 8;
        const int bLN   = ((lane >> 4) << 3) + (lane & 7);
        const int bKoff = ((lane >> 3) & 1) * 8;

        #pragma unroll
        for (int kk = 0; kk < 2; kk++) {
            const int kb = kk * 16;
            uint32_t ah[2][4], al[2][4];
            #pragma unroll
            for (int mt = 0; mt < 2; mt++) {
                int r = (wm * 2 + mt) * 16 + aLRow;
                uint32_t ad = sAh + r * 80 + (kb + aKoff) * 2;
                ldsm4(ah[mt][0], ah[mt][1], ah[mt][2], ah[mt][3], ad);
                ad = sAl + r * 80 + (kb + aKoff) * 2;
                ldsm4(al[mt][0], al[mt][1], al[mt][2], al[mt][3], ad);
            }
            uint32_t bh[2][4], bl[2][4];
            #pragma unroll
            for (int p = 0; p < 2; p++) {
                int n = wn * 32 + p * 16 + bLN;
                uint32_t bd = sBh + n * 80 + (kb + bKoff) * 2;
                ldsm4(bh[p][0], bh[p][1], bh[p][2], bh[p][3], bd);
                bd = sBl + n * 80 + (kb + bKoff) * 2;
                ldsm4(bl[p][0], bl[p][1], bl[p][2], bl[p][3], bd);
            }
            #pragma unroll
            for (int mt = 0; mt < 2; mt++) {
                #pragma unroll
                for (int nt = 0; nt < 4; nt++) {
                    float* d = acc[mt][nt];
                    int p = nt >> 1, q = (nt & 1) * 2;
                    uint32_t b0h = bh[p][q], b1h = bh[p][q + 1];
                    uint32_t b0l = bl[p][q], b1l = bl[p][q + 1];
                    mma_bf16(d[0], d[1], d[2], d[3],
                             ah[mt][0], ah[mt][1], ah[mt][2], ah[mt][3], b0h, b1h);
                    mma_bf16(d[0], d[1], d[2], d[3],
                             al[mt][0], al[mt][1], al[mt][2], al[mt][3], b0h, b1h);
                    mma_bf16(d[0], d[1], d[2], d[3],
                             ah[mt][0], ah[mt][1], ah[mt][2], ah[mt][3], b0l, b1l);
                }
            }
        }
        __syncthreads();
    }

    // epilogue
    #pragma unroll
    for (int mt = 0; mt < 2; mt++) {
        int r0 = rowBase + wm * 32 + mt * 16 + (lane >> 2);
        int r1 = r0 + 8;
        float rs0 = rowscale ? rowscale[r0] : 1.f;
        float rs1 = rowscale ? rowscale[r1] : 1.f;
        #pragma unroll
        for (int nt = 0; nt < 4; nt++) {
            int c0 = colBase + wn * 32 + nt * 8 + (lane & 3) * 2;
            float b0 = (bias && c0 < Nout)     ? bias[c0]     : 0.f;
            float b1 = (bias && c0 + 1 < Nout) ? bias[c0 + 1] : 0.f;
            float v00 = acc[mt][nt][0] * rs0 + b0;
            float v01 = acc[mt][nt][1] * rs0 + b1;
            float v10 = acc[mt][nt][2] * rs1 + b0;
            float v11 = acc[mt][nt][3] * rs1 + b1;
            if (Chalf) {
                *reinterpret_cast<__half2*>(Chalf + (size_t)r0 * ldC + c0) = __floats2half2_rn(v00, v01);
                *reinterpret_cast<__half2*>(Chalf + (size_t)r1 * ldC + c0) = __floats2half2_rn(v10, v11);
            } else if (c0 + 1 < Nout) {
                if (r0 < Mout) *reinterpret_cast<float2*>(C + (size_t)r0 * ldC + c0) = make_float2(v00, v01);
                if (r1 < Mout) *reinterpret_cast<float2*>(C + (size_t)r1 * ldC + c0) = make_float2(v10, v11);
            } else if (c0 < Nout) {
                if (r0 < Mout) C[(size_t)r0 * ldC + c0] = v00;
                if (r1 < Mout) C[(size_t)r1 * ldC + c0] = v10;
            }
        }
    }
}

// ---------------------------------------------------------------------------
extern "C" void kernel_launch(void* const* d_in, const int* in_sizes, int n_in,
                              void* d_out, int out_size)
{
    const float* n_feats = (const float*)d_in[0];
    const int*   src     = (const int*)  d_in[1];
    const int*   dst     = (const int*)  d_in[2];
    const float* Wp      = (const float*)d_in[3];
    const float* bp      = (const float*)d_in[4];
    const float* W1      = (const float*)d_in[5];
    const float* b1      = (const float*)d_in[6];
    const float* W2      = (const float*)d_in[7];
    const float* b2      = (const float*)d_in[8];
    const float* Wc      = (const float*)d_in[9];
    const float* bc      = (const float*)d_in[10];
    float* out = (float*)d_out;
    int E = in_sizes[1];

    float *degout, *bfused;
    __half *Hh, *Xh;
    __nv_bfloat16 *Wfhi, *Wflo, *W2hi, *W2lo, *Wchi, *Wclo;
    cudaGetSymbolAddress((void**)&Xh, g_Xh);
    cudaGetSymbolAddress((void**)&Hh, g_Hh);
    cudaGetSymbolAddress((void**)&degout, g_degout);
    cudaGetSymbolAddress((void**)&bfused, g_bfused);
    cudaGetSymbolAddress((void**)&Wfhi, gWf_hi); cudaGetSymbolAddress((void**)&Wflo, gWf_lo);
    cudaGetSymbolAddress((void**)&W2hi, gW2_hi); cudaGetSymbolAddress((void**)&W2lo, gW2_lo);
    cudaGetSymbolAddress((void**)&Wchi, gWc_hi); cudaGetSymbolAddress((void**)&Wclo, gWc_lo);

    // one-time host-side setup (no device allocation)
    static bool init_done = false;
    static cudaStream_t s2 = nullptr;
    static cudaEvent_t evFork, evCsr;
    if (!init_done) {
        cudaFuncSetAttribute(mma_gemm_kernel<false>, cudaFuncAttributeMaxDynamicSharedMemorySize,
                             SMEM_TOT);
        cudaFuncSetAttribute(mma_gemm_kernel<true>, cudaFuncAttributeMaxDynamicSharedMemorySize,
                             SMEM_TOT);
        cudaStreamCreateWithFlags(&s2, cudaStreamNonBlocking);
        cudaEventCreateWithFlags(&evFork, cudaEventDisableTiming);
        cudaEventCreateWithFlags(&evCsr,  cudaEventDisableTiming);
        init_done = true;
    }

    const int T = 256;
    int nodeBlocks = (NPAD + T - 1) / T;
    int edgeBlocks = (E + T - 1) / T;
    int aggBlocks  = (NPAD + 7) / 8;

    dim3 gH(2, NPAD / 128);
    dim3 gC(1, NPAD / 128);

    // ---- fork: CSR build + degree + W2/Wc presplit on s2 ----
    cudaEventRecord(evFork, 0);
    cudaStreamWaitEvent(s2, evFork, 0);

    presplit_W2c_kernel<<<(24576 + T - 1) / T, T, 0, s2>>>(W2, Wc);
    zero_cnt_kernel<<<nodeBlocks, T, 0, s2>>>();
    count_kernel<<<edgeBlocks, T, 0, s2>>>(src, dst, E);
    rsqrt_kernel<<<nodeBlocks, T, 0, s2>>>();
    scan_phaseA<<<SCAN_B, T, 0, s2>>>();
    scan_phaseB<<<1, T, 0, s2>>>();
    scan_phaseC<<<SCAN_B, T, 0, s2>>>();
    scatter_kernel<<<edgeBlocks, T, 0, s2>>>(src, dst, E);
    cudaEventRecord(evCsr, s2);   // everything on s2 done (weights, degrees, CSR)

    // stream 0: fused weight (Wp@W1 + bp@W1), then the fused GEMM
    // H = n_feats @ Wfused + bfused  (fp16 out, UNSCALED — scale applied in agg1)
    fuse_W_kernel<<<(H_DIM * F_DIM + H_DIM + T - 1) / T, T>>>(Wp, W1, bp);
    mma_gemm_kernel<false><<<gH, T, SMEM_TOT>>>(n_feats, N_NODES, Wfhi, Wflo, F_DIM,
                                                nullptr, Hh, H_DIM, NPAD, H_DIM, bfused, nullptr);

    // ---- GCN layer 1 aggregation (needs CSR + degrees; srcscale=degout) ----
    cudaStreamWaitEvent(0, evCsr, 0);
    csr_agg_kernel<<<aggBlocks, T>>>(b1, degout);

    // ---- GCN layer 2: H = Xh @ W2 row-scaled (fp16 A); agg without srcscale ----
    mma_gemm_kernel<true><<<gH, T, SMEM_TOT>>>(Xh, NPAD, W2hi, W2lo, H_DIM,
                                               nullptr, Hh, H_DIM, NPAD, H_DIM, nullptr, degout);
    csr_agg_kernel<<<aggBlocks, T>>>(b2, nullptr);

    // classifier: out = Xh @ Wc + bc  (fp16 A, fp32 out)
    mma_gemm_kernel<true><<<gC, T, SMEM_TOT>>>(Xh, NPAD, Wchi, Wclo, H_DIM,
                                               out, nullptr, C_DIM, N_NODES, C_DIM, bc, nullptr);
}

// round 17
// speedup vs baseline: 1.7748x; 1.0560x over previous
#include <cuda_runtime.h>
#include <cuda_fp16.h>
#include <cstdint>

#define N_NODES 50000
#define NPAD    50048            // 391 * 128
#define H_DIM   128
#define F_DIM   256
#define C_DIM   40
#define CPAD    64
#define E_CAP   800000
#define SCAN_B  196              // ceil(NPAD / 256)

// ---------------------------------------------------------------------------
// Global scratch (static device globals)
// ---------------------------------------------------------------------------
__device__ __half g_Xh[NPAD * H_DIM];    // activations (fp16)
__device__ __half g_Hh[NPAD * H_DIM];    // messages (fp16)
__device__ float  g_degout[NPAD];        // rsqrt(max(deg_out,1))
__device__ float  g_degin [NPAD];
__device__ int    g_cntin[NPAD], g_cntout[NPAD], g_cnt2[NPAD];
__device__ int    g_rowstart[NPAD + 1];
__device__ int    g_srcsorted[E_CAP];
__device__ int    g_blocksum[SCAN_B];
__device__ int    g_blockoff[SCAN_B];
__device__ float  g_bfused[H_DIM];       // bp @ W1
// fused weight Wp@W1, split fp16 hi/lo, TRANSPOSED [n (128) x k (256)]
__device__ __half gWf_hi[H_DIM * F_DIM], gWf_lo[H_DIM * F_DIM];
// W2/Wc pre-split fp16 hi/lo, transposed [N x K]
__device__ __half gW2_hi[H_DIM * H_DIM], gW2_lo[H_DIM * H_DIM];
__device__ __half gWc_hi[CPAD  * H_DIM], gWc_lo[CPAD  * H_DIM];

// ---------------------------------------------------------------------------
// CSR build + degree kernels
// ---------------------------------------------------------------------------
__global__ void zero_cnt_kernel() {
    int i = blockIdx.x * blockDim.x + threadIdx.x;
    if (i < NPAD) { g_cntin[i] = 0; g_cntout[i] = 0; g_cnt2[i] = 0; }
}

__global__ void count_kernel(const int* __restrict__ src, const int* __restrict__ dst, int E) {
    int i = blockIdx.x * blockDim.x + threadIdx.x;
    if (i < E) {
        atomicAdd(&g_cntout[src[i]], 1);
        atomicAdd(&g_cntin[dst[i]], 1);
    }
}

__global__ void rsqrt_kernel() {
    int i = blockIdx.x * blockDim.x + threadIdx.x;
    if (i < NPAD) {
        g_degout[i] = rsqrtf((float)max(g_cntout[i], 1));
        g_degin[i]  = rsqrtf((float)max(g_cntin[i], 1));
    }
}

// ---- 3-phase multi-block exclusive scan of g_cntin -> g_rowstart ----------
__global__ void scan_phaseA() {
    int t = threadIdx.x;
    int idx = blockIdx.x * 256 + t;
    int v = (idx < NPAD) ? g_cntin[idx] : 0;
    #pragma unroll
    for (int o = 16; o; o >>= 1) v += __shfl_down_sync(0xffffffffu, v, o);
    __shared__ int ws[8];
    if ((t & 31) == 0) ws[t >> 5] = v;
    __syncthreads();
    if (t < 8) {
        int s = ws[t];
        #pragma unroll
        for (int o = 4; o; o >>= 1) s += __shfl_down_sync(0xffu, s, o);
        if (t == 0) g_blocksum[blockIdx.x] = s;
    }
}

__global__ void scan_phaseB() {
    int t = threadIdx.x;
    int lane = t & 31, w = t >> 5;
    int v = (t < SCAN_B) ? g_blocksum[t] : 0;
    int x = v;
    #pragma unroll
    for (int o = 1; o < 32; o <<= 1) {
        int y = __shfl_up_sync(0xffffffffu, x, o);
        if (lane >= o) x += y;
    }
    __shared__ int ws[8];
    if (lane == 31) ws[w] = x;
    __syncthreads();
    if (t == 0) {
        int s = 0;
        #pragma unroll
        for (int i = 0; i < 8; i++) { int tmp = ws[i]; ws[i] = s; s += tmp; }
    }
    __syncthreads();
    int incl = x + ws[w];
    if (t < SCAN_B) {
        g_blockoff[t] = incl - v;
        if (t == SCAN_B - 1) g_rowstart[NPAD] = incl;
    }
}

__global__ void scan_phaseC() {
    int t = threadIdx.x;
    int idx = blockIdx.x * 256 + t;
    int lane = t & 31, w = t >> 5;
    int v = (idx < NPAD) ? g_cntin[idx] : 0;
    int x = v;
    #pragma unroll
    for (int o = 1; o < 32; o <<= 1) {
        int y = __shfl_up_sync(0xffffffffu, x, o);
        if (lane >= o) x += y;
    }
    __shared__ int ws[8];
    if (lane == 31) ws[w] = x;
    __syncthreads();
    if (t == 0) {
        int s = 0;
        #pragma unroll
        for (int i = 0; i < 8; i++) { int tmp = ws[i]; ws[i] = s; s += tmp; }
    }
    __syncthreads();
    int excl = x - v + ws[w] + g_blockoff[blockIdx.x];
    if (idx < NPAD) g_rowstart[idx] = excl;
}

__global__ void scatter_kernel(const int* __restrict__ src, const int* __restrict__ dst, int E) {
    int i = blockIdx.x * blockDim.x + threadIdx.x;
    if (i < E) {
        int d = dst[i];
        int pos = g_rowstart[d] + atomicAdd(&g_cnt2[d], 1);
        g_srcsorted[pos] = src[i];
    }
}

// ---------------------------------------------------------------------------
// CSR aggregate + finalize: one warp per dst node, fp16 messages, fp16 X out.
// X[d] = relu( (sum H[src]*ss) * rsqrt(deg_in[d]) + bias )
// ---------------------------------------------------------------------------
__global__ void csr_agg_kernel(const float* __restrict__ bias,
                               const float* __restrict__ srcscale) {
    int warp = (blockIdx.x * blockDim.x + threadIdx.x) >> 5;
    int lane = threadIdx.x & 31;
    if (warp >= NPAD) return;
    int beg = g_rowstart[warp];
    int end = g_rowstart[warp + 1];
    float4 acc = make_float4(0.f, 0.f, 0.f, 0.f);
    const uint2* Hv = reinterpret_cast<const uint2*>(g_Hh);

    auto addrow = [&](int s) {
        uint2 u = Hv[s * 32 + lane];
        __half2 p0 = *reinterpret_cast<__half2*>(&u.x);
        __half2 p1 = *reinterpret_cast<__half2*>(&u.y);
        float2 f0 = __half22float2(p0);
        float2 f1 = __half22float2(p1);
        float ss = srcscale ? __ldg(&srcscale[s]) : 1.f;
        acc.x = fmaf(f0.x, ss, acc.x);
        acc.y = fmaf(f0.y, ss, acc.y);
        acc.z = fmaf(f1.x, ss, acc.z);
        acc.w = fmaf(f1.y, ss, acc.w);
    };

    int e = beg;
    for (; e + 7 < end; e += 8) {
        int s0 = g_srcsorted[e],   s1 = g_srcsorted[e+1], s2 = g_srcsorted[e+2], s3 = g_srcsorted[e+3];
        int s4 = g_srcsorted[e+4], s5 = g_srcsorted[e+5], s6 = g_srcsorted[e+6], s7 = g_srcsorted[e+7];
        addrow(s0); addrow(s1); addrow(s2); addrow(s3);
        addrow(s4); addrow(s5); addrow(s6); addrow(s7);
    }
    for (; e < end; e++) addrow(g_srcsorted[e]);

    float rs = g_degin[warp];
    float4 b = reinterpret_cast<const float4*>(bias)[lane];
    __half2 o0 = __floats2half2_rn(fmaxf(acc.x * rs + b.x, 0.f),
                                   fmaxf(acc.y * rs + b.y, 0.f));
    __half2 o1 = __floats2half2_rn(fmaxf(acc.z * rs + b.z, 0.f),
                                   fmaxf(acc.w * rs + b.w, 0.f));
    uint2 o;
    o.x = *reinterpret_cast<uint32_t*>(&o0);
    o.y = *reinterpret_cast<uint32_t*>(&o1);
    reinterpret_cast<uint2*>(g_Xh)[warp * 32 + lane] = o;
}

// ---------------------------------------------------------------------------
// fused weight: Wfused = Wp @ W1 (256x128), transposed + fp16 hi/lo; bfused = bp@W1
// ---------------------------------------------------------------------------
__global__ void fuse_W_kernel(const float* __restrict__ Wp,
                              const float* __restrict__ W1,
                              const float* __restrict__ bp) {
    int i = blockIdx.x * blockDim.x + threadIdx.x;
    if (i < H_DIM * F_DIM) {
        int k = i >> 7;          // 0..255
        int n = i & 127;         // 0..127
        float s = 0.f;
        #pragma unroll 8
        for (int j = 0; j < H_DIM; j++)
            s = fmaf(Wp[k * H_DIM + j], W1[j * H_DIM + n], s);
        int idx = n * F_DIM + k;           // [n][k] transposed layout
        __half h = __float2half_rn(s);
        gWf_hi[idx] = h;
        gWf_lo[idx] = __float2half_rn(s - __half2float(h));
    } else if (i < H_DIM * F_DIM + H_DIM) {
        int n = i - H_DIM * F_DIM;
        float s = 0.f;
        for (int j = 0; j < H_DIM; j++)
            s = fmaf(bp[j], W1[j * H_DIM + n], s);
        g_bfused[n] = s;
    }
}

// ---------------------------------------------------------------------------
// weight pre-split: W[K x N] -> fp16 hi/lo [Npad x K] (transposed, padded)
// ---------------------------------------------------------------------------
__device__ __forceinline__ void wsplit_one(const float* W, __half* hi, __half* lo,
                                           int K, int N, int Npad, int i) {
    int n = i / K, k = i - n * K;
    float v = (n < N) ? W[(size_t)k * N + n] : 0.f;
    __half h = __float2half_rn(v);
    hi[i] = h;
    lo[i] = __float2half_rn(v - __half2float(h));
}

// merged presplit for W2 (16384) and Wc (8192) in one launch
__global__ void presplit_W2c_kernel(const float* __restrict__ W2,
                                    const float* __restrict__ Wc) {
    int i = blockIdx.x * blockDim.x + threadIdx.x;
    if (i < 16384) {
        wsplit_one(W2, gW2_hi, gW2_lo, H_DIM, H_DIM, H_DIM, i);
    } else if (i < 24576) {
        wsplit_one(Wc, gWc_hi, gWc_lo, H_DIM, C_DIM, CPAD, i - 16384);
    }
}

// ---------------------------------------------------------------------------
// split-FP16 GEMM: C[M,N] = A[M,K] @ Wt[N x K]
// BM=128, BN=64, BK=32, 256 threads (8 warps: 4m x 2n), warp tile 32x32.
// A path: fp32 (split to fp16 hi/lo, 3 products: hh+lh+hl)
//         or fp16-exact (AEXACT: no A split, 2 products: a*bh + a*bl).
// All retained fp16 products are exact in fp32 accum (22 < 24 mantissa bits).
// ---------------------------------------------------------------------------
#define OFF_AH   0
#define OFF_AL   10240                    // 128 * 80
#define OFF_BH   20480
#define OFF_BL   25600                    // + 64 * 80
#define STG_BYTES 30720
#define SMEM_TOT (2 * STG_BYTES)          // 61440

__device__ __forceinline__ void cp16(uint32_t saddr, const void* g) {
    asm volatile("cp.async.ca.shared.global [%0], [%1], 16;" :: "r"(saddr), "l"(g) : "memory");
}

__device__ __forceinline__ void ldsm4(uint32_t& r0, uint32_t& r1, uint32_t& r2, uint32_t& r3,
                                      uint32_t saddr) {
    asm volatile("ldmatrix.sync.aligned.m8n8.x4.shared.b16 {%0,%1,%2,%3}, [%4];"
                 : "=r"(r0), "=r"(r1), "=r"(r2), "=r"(r3) : "r"(saddr));
}

__device__ __forceinline__ void mma_f16(
    float& d0, float& d1, float& d2, float& d3,
    uint32_t a0, uint32_t a1, uint32_t a2, uint32_t a3,
    uint32_t b0, uint32_t b1)
{
    asm volatile(
        "mma.sync.aligned.m16n8k16.row.col.f32.f16.f16.f32 "
        "{%0,%1,%2,%3}, {%4,%5,%6,%7}, {%8,%9}, {%0,%1,%2,%3};"
        : "+f"(d0), "+f"(d1), "+f"(d2), "+f"(d3)
        : "r"(a0), "r"(a1), "r"(a2), "r"(a3), "r"(b0), "r"(b1));
}

// pack two floats' fp16 hi parts / lo parts
__device__ __forceinline__ void split_pack2h(float x, float y, uint32_t& hi2, uint32_t& lo2) {
    __half2 h = __floats2half2_rn(x, y);
    float rx = x - __half2float(__low2half(h));
    float ry = y - __half2float(__high2half(h));
    __half2 l = __floats2half2_rn(rx, ry);
    hi2 = *reinterpret_cast<uint32_t*>(&h);
    lo2 = *reinterpret_cast<uint32_t*>(&l);
}

template<bool AEXACT>
__global__ __launch_bounds__(256) void mma_gemm_kernel(
    const void* __restrict__ Araw, int Mvalid,
    const __half* __restrict__ Bhi, const __half* __restrict__ Blo, int K,
    float* __restrict__ C, __half* __restrict__ Chalf, int ldC, int Mout, int Nout,
    const float* __restrict__ bias, const float* __restrict__ rowscale)
{
    extern __shared__ uint8_t smem_raw[];
    const uint32_t smem_b = (uint32_t)__cvta_generic_to_shared(smem_raw);

    const int tid  = threadIdx.x;
    const int lane = tid & 31;
    const int warp = tid >> 5;
    const int wm   = warp >> 1;          // 0..3
    const int wn   = warp & 1;           // 0..1
    const int rowBase = blockIdx.y * 128;
    const int colBase = blockIdx.x * 64;
    const int nStages = K >> 5;

    float acc[2][4][4];
    #pragma unroll
    for (int i = 0; i < 2; i++)
        #pragma unroll
        for (int j = 0; j < 4; j++)
            #pragma unroll
            for (int l = 0; l < 4; l++) acc[i][j][l] = 0.f;

    // fp32-A slots: 4 float4/thread (row = idx>>3, c4 = idx&7, 32 floats/row)
    // fp16-A slots: 2 uint4/thread  (row = idx>>2, c16 = idx&3, 4x16B per row)
    int aRow[4], aC4[4];
    #pragma unroll
    for (int i = 0; i < 4; i++) {
        int idx = tid + i * 256;
        if (AEXACT) { aRow[i] = idx >> 2; aC4[i] = idx & 3; }
        else        { aRow[i] = idx >> 3; aC4[i] = idx & 7; }
    }
    // B loader slot: n = tid>>2, c16 = tid&3
    const int bN = tid >> 2, bC = tid & 3;

    float4 pa[4];
    uint4  ph[2];
    auto loadA = [&](int s) {
        const int k0 = s * 32;
        if (AEXACT) {
            const __half* A = (const __half*)Araw;
            #pragma unroll
            for (int i = 0; i < 2; i++) {
                int gr = rowBase + aRow[i];
                ph[i] = (gr < Mvalid)
                      ? *reinterpret_cast<const uint4*>(A + (size_t)gr * K + k0 + aC4[i] * 8)
                      : make_uint4(0u, 0u, 0u, 0u);
            }
        } else {
            const float* A = (const float*)Araw;
            #pragma unroll
            for (int i = 0; i < 4; i++) {
                int gr = rowBase + aRow[i];
                pa[i] = (gr < Mvalid)
                      ? *reinterpret_cast<const float4*>(A + (size_t)gr * K + k0 + aC4[i] * 4)
                      : make_float4(0.f, 0.f, 0.f, 0.f);
            }
        }
    };
    auto storeA = [&](int b) {
        if (AEXACT) {
            // A already fp16: store directly, no split, no Al region.
            #pragma unroll
            for (int i = 0; i < 2; i++) {
                uint32_t off = aRow[i] * 80 + aC4[i] * 16;
                *reinterpret_cast<uint4*>(smem_raw + off + b * STG_BYTES + OFF_AH) = ph[i];
            }
        } else {
            #pragma unroll
            for (int i = 0; i < 4; i++) {
                uint32_t h01, l01, h23, l23;
                split_pack2h(pa[i].x, pa[i].y, h01, l01);
                split_pack2h(pa[i].z, pa[i].w, h23, l23);
                uint32_t off = aRow[i] * 80 + aC4[i] * 8;
                *reinterpret_cast<uint2*>(smem_raw + off + b * STG_BYTES + OFF_AH) = make_uint2(h01, h23);
                *reinterpret_cast<uint2*>(smem_raw + off + b * STG_BYTES + OFF_AL) = make_uint2(l01, l23);
            }
        }
    };
    auto issueB = [&](int s, int b) {
        const int k0 = s * 32;
        const uint32_t sb = smem_b + b * STG_BYTES;
        size_t g = (size_t)(colBase + bN) * K + k0 + bC * 8;
        uint32_t off = bN * 80 + bC * 16;
        cp16(sb + OFF_BH + off, Bhi + g);
        cp16(sb + OFF_BL + off, Blo + g);
        asm volatile("cp.async.commit_group;" ::: "memory");
    };

    loadA(0);
    issueB(0, 0);

    for (int s = 0; s < nStages; s++) {
        const int b = s & 1;
        storeA(b);
        if (s + 1 < nStages) {
            loadA(s + 1);
            issueB(s + 1, b ^ 1);
            asm volatile("cp.async.wait_group 1;" ::: "memory");
        } else {
            asm volatile("cp.async.wait_group 0;" ::: "memory");
        }
        __syncthreads();

        const uint32_t sAh = smem_b + b * STG_BYTES + OFF_AH;
        const uint32_t sAl = smem_b + b * STG_BYTES + OFF_AL;
        const uint32_t sBh = smem_b + b * STG_BYTES + OFF_BH;
        const uint32_t sBl = smem_b + b * STG_BYTES + OFF_BL;

        const int aLRow = lane & 15;
        const int aKoff = (lane >> 4) * 8;
        const int bLN   = ((lane >> 4) << 3) + (lane & 7);
        const int bKoff = ((lane >> 3) & 1) * 8;

        #pragma unroll
        for (int kk = 0; kk < 2; kk++) {
            const int kb = kk * 16;
            uint32_t ah[2][4], al[2][4];
            #pragma unroll
            for (int mt = 0; mt < 2; mt++) {
                int r = (wm * 2 + mt) * 16 + aLRow;
                uint32_t ad = sAh + r * 80 + (kb + aKoff) * 2;
                ldsm4(ah[mt][0], ah[mt][1], ah[mt][2], ah[mt][3], ad);
                if (!AEXACT) {
                    ad = sAl + r * 80 + (kb + aKoff) * 2;
                    ldsm4(al[mt][0], al[mt][1], al[mt][2], al[mt][3], ad);
                }
            }
            uint32_t bh[2][4], bl[2][4];
            #pragma unroll
            for (int p = 0; p < 2; p++) {
                int n = wn * 32 + p * 16 + bLN;
                uint32_t bd = sBh + n * 80 + (kb + bKoff) * 2;
                ldsm4(bh[p][0], bh[p][1], bh[p][2], bh[p][3], bd);
                bd = sBl + n * 80 + (kb + bKoff) * 2;
                ldsm4(bl[p][0], bl[p][1], bl[p][2], bl[p][3], bd);
            }
            #pragma unroll
            for (int mt = 0; mt < 2; mt++) {
                #pragma unroll
                for (int nt = 0; nt < 4; nt++) {
                    float* d = acc[mt][nt];
                    int p = nt >> 1, q = (nt & 1) * 2;
                    uint32_t b0h = bh[p][q], b1h = bh[p][q + 1];
                    uint32_t b0l = bl[p][q], b1l = bl[p][q + 1];
                    mma_f16(d[0], d[1], d[2], d[3],
                            ah[mt][0], ah[mt][1], ah[mt][2], ah[mt][3], b0h, b1h);
                    if (!AEXACT)
                        mma_f16(d[0], d[1], d[2], d[3],
                                al[mt][0], al[mt][1], al[mt][2], al[mt][3], b0h, b1h);
                    mma_f16(d[0], d[1], d[2], d[3],
                            ah[mt][0], ah[mt][1], ah[mt][2], ah[mt][3], b0l, b1l);
                }
            }
        }
        __syncthreads();
    }

    // epilogue
    #pragma unroll
    for (int mt = 0; mt < 2; mt++) {
        int r0 = rowBase + wm * 32 + mt * 16 + (lane >> 2);
        int r1 = r0 + 8;
        float rs0 = rowscale ? rowscale[r0] : 1.f;
        float rs1 = rowscale ? rowscale[r1] : 1.f;
        #pragma unroll
        for (int nt = 0; nt < 4; nt++) {
            int c0 = colBase + wn * 32 + nt * 8 + (lane & 3) * 2;
            float b0 = (bias && c0 < Nout)     ? bias[c0]     : 0.f;
            float b1 = (bias && c0 + 1 < Nout) ? bias[c0 + 1] : 0.f;
            float v00 = acc[mt][nt][0] * rs0 + b0;
            float v01 = acc[mt][nt][1] * rs0 + b1;
            float v10 = acc[mt][nt][2] * rs1 + b0;
            float v11 = acc[mt][nt][3] * rs1 + b1;
            if (Chalf) {
                *reinterpret_cast<__half2*>(Chalf + (size_t)r0 * ldC + c0) = __floats2half2_rn(v00, v01);
                *reinterpret_cast<__half2*>(Chalf + (size_t)r1 * ldC + c0) = __floats2half2_rn(v10, v11);
            } else if (c0 + 1 < Nout) {
                if (r0 < Mout) *reinterpret_cast<float2*>(C + (size_t)r0 * ldC + c0) = make_float2(v00, v01);
                if (r1 < Mout) *reinterpret_cast<float2*>(C + (size_t)r1 * ldC + c0) = make_float2(v10, v11);
            } else if (c0 < Nout) {
                if (r0 < Mout) C[(size_t)r0 * ldC + c0] = v00;
                if (r1 < Mout) C[(size_t)r1 * ldC + c0] = v10;
            }
        }
    }
}

// ---------------------------------------------------------------------------
extern "C" void kernel_launch(void* const* d_in, const int* in_sizes, int n_in,
                              void* d_out, int out_size)
{
    const float* n_feats = (const float*)d_in[0];
    const int*   src     = (const int*)  d_in[1];
    const int*   dst     = (const int*)  d_in[2];
    const float* Wp      = (const float*)d_in[3];
    const float* bp      = (const float*)d_in[4];
    const float* W1      = (const float*)d_in[5];
    const float* b1      = (const float*)d_in[6];
    const float* W2      = (const float*)d_in[7];
    const float* b2      = (const float*)d_in[8];
    const float* Wc      = (const float*)d_in[9];
    const float* bc      = (const float*)d_in[10];
    float* out = (float*)d_out;
    int E = in_sizes[1];

    float *degout, *bfused;
    __half *Hh, *Xh;
    __half *Wfhi, *Wflo, *W2hi, *W2lo, *Wchi, *Wclo;
    cudaGetSymbolAddress((void**)&Xh, g_Xh);
    cudaGetSymbolAddress((void**)&Hh, g_Hh);
    cudaGetSymbolAddress((void**)&degout, g_degout);
    cudaGetSymbolAddress((void**)&bfused, g_bfused);
    cudaGetSymbolAddress((void**)&Wfhi, gWf_hi); cudaGetSymbolAddress((void**)&Wflo, gWf_lo);
    cudaGetSymbolAddress((void**)&W2hi, gW2_hi); cudaGetSymbolAddress((void**)&W2lo, gW2_lo);
    cudaGetSymbolAddress((void**)&Wchi, gWc_hi); cudaGetSymbolAddress((void**)&Wclo, gWc_lo);

    // one-time host-side setup (no device allocation)
    static bool init_done = false;
    static cudaStream_t s2 = nullptr;
    static cudaEvent_t evFork, evCsr;
    if (!init_done) {
        cudaFuncSetAttribute(mma_gemm_kernel<false>, cudaFuncAttributeMaxDynamicSharedMemorySize,
                             SMEM_TOT);
        cudaFuncSetAttribute(mma_gemm_kernel<true>, cudaFuncAttributeMaxDynamicSharedMemorySize,
                             SMEM_TOT);
        cudaStreamCreateWithFlags(&s2, cudaStreamNonBlocking);
        cudaEventCreateWithFlags(&evFork, cudaEventDisableTiming);
        cudaEventCreateWithFlags(&evCsr,  cudaEventDisableTiming);
        init_done = true;
    }

    const int T = 256;
    int nodeBlocks = (NPAD + T - 1) / T;
    int edgeBlocks = (E + T - 1) / T;
    int aggBlocks  = (NPAD + 7) / 8;

    dim3 gH(2, NPAD / 128);
    dim3 gC(1, NPAD / 128);

    // ---- fork: CSR build + degree + W2/Wc presplit on s2 ----
    cudaEventRecord(evFork, 0);
    cudaStreamWaitEvent(s2, evFork, 0);

    presplit_W2c_kernel<<<(24576 + T - 1) / T, T, 0, s2>>>(W2, Wc);
    zero_cnt_kernel<<<nodeBlocks, T, 0, s2>>>();
    count_kernel<<<edgeBlocks, T, 0, s2>>>(src, dst, E);
    rsqrt_kernel<<<nodeBlocks, T, 0, s2>>>();
    scan_phaseA<<<SCAN_B, T, 0, s2>>>();
    scan_phaseB<<<1, T, 0, s2>>>();
    scan_phaseC<<<SCAN_B, T, 0, s2>>>();
    scatter_kernel<<<edgeBlocks, T, 0, s2>>>(src, dst, E);
    cudaEventRecord(evCsr, s2);   // everything on s2 done (weights, degrees, CSR)

    // stream 0: fused weight (Wp@W1 + bp@W1), then the fused GEMM
    // H = n_feats @ Wfused + bfused  (fp16 out, UNSCALED — scale applied in agg1)
    fuse_W_kernel<<<(H_DIM * F_DIM + H_DIM + T - 1) / T, T>>>(Wp, W1, bp);
    mma_gemm_kernel<false><<<gH, T, SMEM_TOT>>>(n_feats, N_NODES, Wfhi, Wflo, F_DIM,
                                                nullptr, Hh, H_DIM, NPAD, H_DIM, bfused, nullptr);

    // ---- GCN layer 1 aggregation (needs CSR + degrees; srcscale=degout) ----
    cudaStreamWaitEvent(0, evCsr, 0);
    csr_agg_kernel<<<aggBlocks, T>>>(b1, degout);

    // ---- GCN layer 2: H = Xh @ W2 row-scaled (fp16-exact A); agg plain ----
    mma_gemm_kernel<true><<<gH, T, SMEM_TOT>>>(Xh, NPAD, W2hi, W2lo, H_DIM,
                                               nullptr, Hh, H_DIM, NPAD, H_DIM, nullptr, degout);
    csr_agg_kernel<<<aggBlocks, T>>>(b2, nullptr);

    // classifier: out = Xh @ Wc + bc  (fp16-exact A, fp32 out)
    mma_gemm_kernel<true><<<gC, T, SMEM_TOT>>>(Xh, NPAD, Wchi, Wclo, H_DIM,
                                               out, nullptr, C_DIM, N_NODES, C_DIM, bc, nullptr);
}